// round 14
// baseline (speedup 1.0000x reference)
#include <cuda_runtime.h>
#include <cstdint>

#define Bq 4
#define Cq 64
#define Hq 128
#define Wq 128
#define HWq (Hq*Wq)
#define CHWq (Cq*HWq)
#define HW8 (HWq*8)
#define KK 7
#define TAPS 49
#define NGRP 24
#define NKB  72
#define WB2_CONV (NKB*256)

// scratch (allocation-free rule: __device__ globals). NHWC8 for intermediates.
__device__ float  g_rx [Bq*CHWq];
__device__ float  g_kf [Bq*CHWq];
__device__ float  g_b1f[Bq*CHWq];
__device__ float  g_b1m[Bq*CHWq];
__device__ float  g_b2f[Bq*CHWq];
__device__ float  g_b2m[Bq*CHWq];
__device__ float  g_lp [Bq*HWq*52];     // [b][hw][52] tap-innermost
__device__ float2 g_wB2[4*WB2_CONV];
__device__ float2 g_wL1[2048];
__device__ float2 g_wL2[1792];

// ---------------------------------------------------------------------------
__device__ __forceinline__ uint32_t tf32_hi(float v) {
    uint32_t r; asm("cvt.rna.tf32.f32 %0, %1;" : "=r"(r) : "f"(v)); return r;
}
__device__ __forceinline__ float tf32f(float v) {
    return __uint_as_float(tf32_hi(v));
}
__device__ __forceinline__ void cp16(void* dst, const void* src) {
    unsigned d = (unsigned)__cvta_generic_to_shared(dst);
    asm volatile("cp.async.ca.shared.global [%0], [%1], 16;" :: "r"(d), "l"(src));
}
#define CP_COMMIT asm volatile("cp.async.commit_group;")
#define CP_WAIT0  asm volatile("cp.async.wait_group 0;")

__device__ __forceinline__ void mma_tf32(float d[4], const uint32_t a[4],
                                         uint32_t b0, uint32_t b1)
{
    asm volatile(
        "mma.sync.aligned.m16n8k8.row.col.f32.tf32.tf32.f32 "
        "{%0,%1,%2,%3}, {%4,%5,%6,%7}, {%8,%9}, {%0,%1,%2,%3};"
        : "+f"(d[0]), "+f"(d[1]), "+f"(d[2]), "+f"(d[3])
        : "r"(a[0]), "r"(a[1]), "r"(a[2]), "r"(a[3]), "r"(b0), "r"(b1));
}
__device__ __forceinline__ unsigned long long dup2(float a) {
    unsigned long long r;
    asm("mov.b64 %0, {%1, %1};" : "=l"(r) : "f"(a)); return r;
}
__device__ __forceinline__ void fma2(unsigned long long& d,
                                     unsigned long long a, unsigned long long b) {
    asm("fma.rn.f32x2 %0, %1, %2, %0;" : "+l"(d) : "l"(a), "l"(b));
}
__device__ __forceinline__ float2 unpack2(unsigned long long v) {
    float2 f;
    asm("mov.b64 {%0, %1}, %2;" : "=f"(f.x), "=f"(f.y) : "l"(v)); return f;
}

// ---------------------------------------------------------------------------
// prep: both NCHW -> NHWC8 transposes in one launch (grid.y selects tensor)
// ---------------------------------------------------------------------------
__global__ void prep_in_kernel(const float* __restrict__ x, const float* __restrict__ kf,
                               float* __restrict__ rx, float* __restrict__ kfo)
{
    int i  = blockIdx.x*256 + threadIdx.x;
    bool second = (blockIdx.y != 0);
    const float* in  = second ? kf  : x;
    float*       out = second ? kfo : rx;
    int hw = i & (HWq-1);
    int bo = i >> 14;
    const float* p = in + bo*8*HWq + hw;
    float v[8];
#pragma unroll
    for (int c = 0; c < 8; c++) {
        float t = p[c*HWq];
        v[c] = second ? t : fmaxf(t, 0.f);
    }
    float4* o = (float4*)(out + (size_t)i*8);
    o[0] = make_float4(v[0], v[1], v[2], v[3]);
    o[1] = make_float4(v[4], v[5], v[6], v[7]);
}

// all weight packing in one launch: conv frags then lp frags
__global__ void prep_wt_all_kernel(
    const float* __restrict__ w0, const float* __restrict__ w1,
    const float* __restrict__ w2, const float* __restrict__ w3,
    const float* __restrict__ lw1, const float* __restrict__ lw2,
    float2* __restrict__ wB2, float2* __restrict__ wL1, float2* __restrict__ wL2)
{
    int i = blockIdx.x*256 + threadIdx.x;
    if (i < 4*WB2_CONV) {
        int conv = i / WB2_CONV;
        int r    = i - conv*WB2_CONV;
        int kb   = r >> 8;
        int r2   = r & 255;
        int nb   = r2 >> 5;
        int lane = r2 & 31;
        int g  = kb / 3, dx = kb - g*3;
        int dy = g >> 3, oct = g & 7;
        int tap = dy*3 + dx;
        int n   = nb*8 + (lane >> 2);
        int ci0 = oct*8 + (lane & 3);
        const float* w = (conv == 0) ? w0 : (conv == 1) ? w1 : (conv == 2) ? w2 : w3;
        float v0 = w[(n*Cq + ci0    )*9 + tap];
        float v1 = w[(n*Cq + ci0 + 4)*9 + tap];
        wB2[i] = make_float2(tf32f(v0), tf32f(v1));
    } else {
        int j = i - 4*WB2_CONV;
        if (j < 2048) {
            int kb = j >> 8, r2 = j & 255, nb = r2 >> 5, lane = r2 & 31;
            int n = nb*8 + (lane >> 2), ci = kb*8 + (lane & 3);
            wL1[j] = make_float2(tf32f(lw1[n*64 + ci]), tf32f(lw1[n*64 + ci + 4]));
        } else if (j < 3840) {
            int q = j - 2048;
            int kb = q / 224, r2 = q - kb*224, nb = r2 >> 5, lane = r2 & 31;
            int n = nb*8 + (lane >> 2), ci = kb*8 + (lane & 3);
            float v0 = (n < 49) ? lw2[n*64 + ci]     : 0.f;
            float v1 = (n < 49) ? lw2[n*64 + ci + 4] : 0.f;
            wL2[q] = make_float2(tf32f(v0), tf32f(v1));
        }
    }
}

// ---------------------------------------------------------------------------
// conv3x3 via mma.sync tf32 1-pass. NHWC8 in/out. (R12 shape: 128 thr, 1 row
// per CTA, grid (Hq, 2*Bq).) One __syncthreads per group (parity-safe), 6
// CTAs/SM for latency hiding.
// ---------------------------------------------------------------------------
template<bool RELU_OUT>
__global__ __launch_bounds__(128, 6)
void conv_mma_kernel(const float* __restrict__ inA, const float* __restrict__ inB,
                     const float2* __restrict__ wBA, const float2* __restrict__ wBB,
                     const float* __restrict__ biasA, const float* __restrict__ biasB,
                     float* __restrict__ outA, float* __restrict__ outB)
{
    __shared__ alignas(16) float  sA[2][130*8];
    __shared__ alignas(16) float2 sB[2][768];

    const int y  = blockIdx.x;
    const int z  = blockIdx.y;
    const int b  = z & 3;
    const bool pB = (z >= 4);
    const float*  in   = (pB ? inB  : inA) + b*CHWq;
    const float2* wB   =  pB ? wBB  : wBA;
    const float*  bias =  pB ? biasB : biasA;
    float*        out  = (pB ? outB : outA) + b*CHWq;

    const int tid  = threadIdx.x;
    const int wid  = tid >> 5;
    const int lane = tid & 31;

    if (tid < 32) {
        int bb = tid >> 4, rr = (tid >> 3) & 1, cc = tid & 7;
        sA[bb][(rr ? 129*8 : 0) + cc] = 0.f;
    }

    float d[2][8][4];
#pragma unroll
    for (int mi = 0; mi < 2; mi++)
#pragma unroll
        for (int ni = 0; ni < 8; ni++)
#pragma unroll
            for (int r = 0; r < 4; r++) d[mi][ni][r] = 0.f;

    float4 va, vb_;
    auto preloadA = [&](int g) {
        int dy = g >> 3, oct = g & 7;
        int yin = y + dy - 1;
        if (yin >= 0 && yin < Hq) {
            const float4* p = (const float4*)(in + oct*HW8 + (yin*Wq + tid)*8);
            va  = __ldg(p);
            vb_ = __ldg(p + 1);
        } else {
            va  = make_float4(0.f, 0.f, 0.f, 0.f);
            vb_ = make_float4(0.f, 0.f, 0.f, 0.f);
        }
    };
    auto storeA = [&](int buf) {
        int px = tid + 1;
        int sw = (px >> 2) & 1;
        float* base = &sA[buf][px*8];
        float4 p0 = make_float4(tf32f(va.x), tf32f(vb_.x), tf32f(va.y), tf32f(vb_.y));
        float4 p1 = make_float4(tf32f(va.z), tf32f(vb_.z), tf32f(va.w), tf32f(vb_.w));
        *(float4*)(base + ((0 ^ sw) << 2)) = p0;
        *(float4*)(base + ((1 ^ sw) << 2)) = p1;
    };
    auto stageB = [&](int buf, int g) {
        const float4* src = (const float4*)(wB + g*768);
        float4* dst = (float4*)sB[buf];
        cp16(dst + tid,       src + tid);
        cp16(dst + 128 + tid, src + 128 + tid);
        cp16(dst + 256 + tid, src + 256 + tid);
        CP_COMMIT;
    };

    preloadA(0);
    storeA(0);
    stageB(0, 0);

    for (int g = 0; g < NGRP; g++) {
        const int buf = g & 1;
        CP_WAIT0;
        __syncthreads();
        if (g + 1 < NGRP) { stageB(buf ^ 1, g + 1); preloadA(g + 1); }

#pragma unroll
        for (int dx = 0; dx < 3; dx++) {
            uint32_t a[2][4];
#pragma unroll
            for (int mi = 0; mi < 2; mi++) {
                int pxl = wid*32 + mi*16 + (lane >> 2) + dx;
                int c   = lane & 3;
                int sw  = (pxl >> 2) & 1;
                int off = (((c >> 1) ^ sw) << 2) + ((c & 1) << 1);
                float2 q0 = *(float2*)&sA[buf][pxl*8 + off];
                float2 q1 = *(float2*)&sA[buf][(pxl + 8)*8 + off];
                a[mi][0] = __float_as_uint(q0.x);
                a[mi][2] = __float_as_uint(q0.y);
                a[mi][1] = __float_as_uint(q1.x);
                a[mi][3] = __float_as_uint(q1.y);
            }
#pragma unroll
            for (int ni = 0; ni < 8; ni++) {
                float2 bq = sB[buf][(dx*8 + ni)*32 + lane];
                uint32_t b0 = __float_as_uint(bq.x), b1 = __float_as_uint(bq.y);
#pragma unroll
                for (int mi = 0; mi < 2; mi++)
                    mma_tf32(d[mi][ni], a[mi], b0, b1);
            }
        }

        if (g + 1 < NGRP) storeA(buf ^ 1);
        // no end sync: iteration g+1's top barrier orders these writes
        // (they target buf^1) against g+1's reads, and any write to buf
        // happens at g+2, after two barriers.
    }

    const int row  = lane >> 2;
    const int colb = (lane & 3) << 1;
#pragma unroll
    for (int mi = 0; mi < 2; mi++) {
        int px0 = wid*32 + mi*16 + row;
#pragma unroll
        for (int ni = 0; ni < 8; ni++) {
            float b0 = __ldg(bias + ni*8 + colb);
            float b1 = __ldg(bias + ni*8 + colb + 1);
            float2 r0 = make_float2(d[mi][ni][0] + b0, d[mi][ni][1] + b1);
            float2 r1 = make_float2(d[mi][ni][2] + b0, d[mi][ni][3] + b1);
            if (RELU_OUT) {
                r0.x = fmaxf(r0.x, 0.f); r0.y = fmaxf(r0.y, 0.f);
                r1.x = fmaxf(r1.x, 0.f); r1.y = fmaxf(r1.y, 0.f);
            }
            float* o8 = out + ni*HW8;
            *(float2*)(o8 + (y*Wq + px0    )*8 + colb) = r0;
            *(float2*)(o8 + (y*Wq + px0 + 8)*8 + colb) = r1;
        }
    }
}

// ---------------------------------------------------------------------------
// lp path via mma.sync tf32 (unchanged)
// ---------------------------------------------------------------------------
__global__ __launch_bounds__(128, 3)
void lp_mma_kernel(const float* __restrict__ kf,
                   const float2* __restrict__ wL1, const float2* __restrict__ wL2,
                   const float* __restrict__ b1, const float* __restrict__ b2,
                   float* __restrict__ lp)
{
    __shared__ alignas(16) float sU[8192];
    __shared__ float s_b1[64];
    __shared__ float s_b2[56];

    const int y = blockIdx.x, b = blockIdx.y;
    const int tid = threadIdx.x, wid = tid >> 5, lane = tid & 31;
    const float* kfb = kf + b*CHWq;

    if (tid < 64) s_b1[tid] = b1[tid];
    if (tid < 56) s_b2[tid] = (tid < 49) ? b2[tid] : 0.f;

    {
        int px = tid, sw = (px >> 2) & 1;
#pragma unroll
        for (int oct = 0; oct < 8; oct++) {
            const float4* p = (const float4*)(kfb + oct*HW8 + (y*Wq + px)*8);
            float4 u0 = __ldg(p), u1 = __ldg(p + 1);
            float* base = &sU[oct*1024 + px*8];
            float4 p0 = make_float4(tf32f(u0.x), tf32f(u1.x), tf32f(u0.y), tf32f(u1.y));
            float4 p1 = make_float4(tf32f(u0.z), tf32f(u1.z), tf32f(u0.w), tf32f(u1.w));
            *(float4*)(base + ((0 ^ sw) << 2)) = p0;
            *(float4*)(base + ((1 ^ sw) << 2)) = p1;
        }
    }
    __syncthreads();

    float d1[2][8][4];
#pragma unroll
    for (int mi = 0; mi < 2; mi++)
#pragma unroll
        for (int ni = 0; ni < 8; ni++)
#pragma unroll
            for (int r = 0; r < 4; r++) d1[mi][ni][r] = 0.f;

#pragma unroll
    for (int oct = 0; oct < 8; oct++) {
        uint32_t a[2][4];
#pragma unroll
        for (int mi = 0; mi < 2; mi++) {
            int pxl = wid*32 + mi*16 + (lane >> 2);
            int c = lane & 3, sw = (pxl >> 2) & 1;
            int off = (((c >> 1) ^ sw) << 2) + ((c & 1) << 1);
            float2 q0 = *(float2*)&sU[oct*1024 + pxl*8 + off];
            float2 q1 = *(float2*)&sU[oct*1024 + (pxl + 8)*8 + off];
            a[mi][0] = __float_as_uint(q0.x);
            a[mi][2] = __float_as_uint(q0.y);
            a[mi][1] = __float_as_uint(q1.x);
            a[mi][3] = __float_as_uint(q1.y);
        }
#pragma unroll
        for (int ni = 0; ni < 8; ni++) {
            float2 bq = __ldg(&wL1[(oct*8 + ni)*32 + lane]);
            uint32_t b0 = __float_as_uint(bq.x), b1v = __float_as_uint(bq.y);
#pragma unroll
            for (int mi = 0; mi < 2; mi++)
                mma_tf32(d1[mi][ni], a[mi], b0, b1v);
        }
    }
    __syncthreads();

    {
        const int colb = (lane & 3) << 1;
#pragma unroll
        for (int mi = 0; mi < 2; mi++) {
            int row0 = wid*32 + mi*16 + (lane >> 2);
            int sw   = (row0 >> 2) & 1;
            int blk  = ((((colb & 3) >> 1) ^ sw) << 2);
            int posE = blk + (colb >= 4 ? 1 : 0);
            int posO = blk + 2 + (colb >= 4 ? 1 : 0);
#pragma unroll
            for (int ni = 0; ni < 8; ni++) {
                float bA = s_b1[ni*8 + colb], bB = s_b1[ni*8 + colb + 1];
                float* base = &sU[ni*1024];
                base[row0*8 + posE]       = tf32f(fmaxf(d1[mi][ni][0] + bA, 0.f));
                base[row0*8 + posO]       = tf32f(fmaxf(d1[mi][ni][1] + bB, 0.f));
                base[(row0 + 8)*8 + posE] = tf32f(fmaxf(d1[mi][ni][2] + bA, 0.f));
                base[(row0 + 8)*8 + posO] = tf32f(fmaxf(d1[mi][ni][3] + bB, 0.f));
            }
        }
    }
    __syncthreads();

    float d2[2][7][4];
#pragma unroll
    for (int mi = 0; mi < 2; mi++)
#pragma unroll
        for (int ni = 0; ni < 7; ni++)
#pragma unroll
            for (int r = 0; r < 4; r++) d2[mi][ni][r] = 0.f;

#pragma unroll
    for (int oct = 0; oct < 8; oct++) {
        uint32_t a[2][4];
#pragma unroll
        for (int mi = 0; mi < 2; mi++) {
            int pxl = wid*32 + mi*16 + (lane >> 2);
            int c = lane & 3, sw = (pxl >> 2) & 1;
            int off = (((c >> 1) ^ sw) << 2) + ((c & 1) << 1);
            float2 q0 = *(float2*)&sU[oct*1024 + pxl*8 + off];
            float2 q1 = *(float2*)&sU[oct*1024 + (pxl + 8)*8 + off];
            a[mi][0] = __float_as_uint(q0.x);
            a[mi][2] = __float_as_uint(q0.y);
            a[mi][1] = __float_as_uint(q1.x);
            a[mi][3] = __float_as_uint(q1.y);
        }
#pragma unroll
        for (int ni = 0; ni < 7; ni++) {
            float2 bq = __ldg(&wL2[(oct*7 + ni)*32 + lane]);
            uint32_t b0 = __float_as_uint(bq.x), b1v = __float_as_uint(bq.y);
#pragma unroll
            for (int mi = 0; mi < 2; mi++)
                mma_tf32(d2[mi][ni], a[mi], b0, b1v);
        }
    }

    const int colb = (lane & 3) << 1;
    float* lpb = lp + (size_t)(b*HWq + y*Wq)*52;
#pragma unroll
    for (int mi = 0; mi < 2; mi++) {
#pragma unroll
        for (int rh = 0; rh < 2; rh++) {
            int px = wid*32 + mi*16 + (lane >> 2) + rh*8;
            float v[7][2];
            float ls = 0.f;
#pragma unroll
            for (int ni = 0; ni < 7; ni++) {
                int col = ni*8 + colb;
                v[ni][0] = d2[mi][ni][rh*2 + 0] + s_b2[col];
                v[ni][1] = d2[mi][ni][rh*2 + 1] + s_b2[col + 1];
                ls += v[ni][0] + v[ni][1];
            }
            ls += __shfl_xor_sync(0xffffffff, ls, 1);
            ls += __shfl_xor_sync(0xffffffff, ls, 2);
            float m = ls * (1.0f/49.0f);
            float* rowp = lpb + (size_t)px*52;
#pragma unroll
            for (int ni = 0; ni < 7; ni++) {
                int col = ni*8 + colb;
                if (col < 52) {
                    float2 o = make_float2(v[ni][0] - m + (1.0f/49.0f),
                                           v[ni][1] - m + (1.0f/49.0f));
                    *(float2*)(rowp + col) = o;
                }
            }
        }
    }
}

// ---------------------------------------------------------------------------
// dynamic 7x7 local conv + residual; feat = fp*mp computed during staging.
// ---------------------------------------------------------------------------
#define TILE 16
__global__ __launch_bounds__(256, 2)
void local_conv_kernel(const float* __restrict__ x,
                       const float* __restrict__ fp, const float* __restrict__ mp,
                       const float* __restrict__ lp, float* __restrict__ out)
{
    __shared__ alignas(16) float s_f[2][22*22*10];
    const int b  = blockIdx.z;
    const int x0 = blockIdx.x * TILE;
    const int y0 = blockIdx.y * TILE;
    const int tid = threadIdx.x;
    const int tx = tid & 15, ty = tid >> 4;
    const int y = y0 + ty, xx = x0 + tx;

    float kl[TAPS];
    {
        const float4* klb = (const float4*)(lp + (size_t)(b*HWq + y*Wq + xx)*52);
        float4 t[13];
#pragma unroll
        for (int q = 0; q < 13; q++) t[q] = __ldg(klb + q);
#pragma unroll
        for (int k = 0; k < TAPS; k++) kl[k] = ((const float*)t)[k];
    }

    const float* fpb = fp + b*CHWq;
    const float* mpb = mp + b*CHWq;
    const float* xb  = x  + b*CHWq;
    float*       ob  = out + b*CHWq;

    float4 pv[2][2];
    auto preloadF = [&](int oct) {
#pragma unroll
        for (int s = 0; s < 2; s++) {
            int idx = tid + s*256;
            if (idx < 484) {
                int r  = idx / 22;
                int cc = idx - r*22;
                int gy = y0 + r - 3, gx = x0 + cc - 3;
                if (gy >= 0 && gy < Hq && gx >= 0 && gx < Wq) {
                    const float4* pf = (const float4*)(fpb + oct*HW8 + (gy*Wq + gx)*8);
                    const float4* pm = (const float4*)(mpb + oct*HW8 + (gy*Wq + gx)*8);
                    float4 a0 = __ldg(pf), a1 = __ldg(pf + 1);
                    float4 m0 = __ldg(pm), m1 = __ldg(pm + 1);
                    pv[s][0] = make_float4(a0.x*m0.x, a0.y*m0.y, a0.z*m0.z, a0.w*m0.w);
                    pv[s][1] = make_float4(a1.x*m1.x, a1.y*m1.y, a1.z*m1.z, a1.w*m1.w);
                } else {
                    pv[s][0] = make_float4(0.f, 0.f, 0.f, 0.f);
                    pv[s][1] = make_float4(0.f, 0.f, 0.f, 0.f);
                }
            }
        }
    };
    auto storeF = [&](int buf) {
#pragma unroll
        for (int s = 0; s < 2; s++) {
            int idx = tid + s*256;
            if (idx < 484) {
                float* dst = &s_f[buf][idx*10];
                *(float2*)(dst + 0) = make_float2(pv[s][0].x, pv[s][0].y);
                *(float2*)(dst + 2) = make_float2(pv[s][0].z, pv[s][0].w);
                *(float2*)(dst + 4) = make_float2(pv[s][1].x, pv[s][1].y);
                *(float2*)(dst + 6) = make_float2(pv[s][1].z, pv[s][1].w);
            }
        }
    };

    preloadF(0);
    storeF(0);

    for (int oct = 0; oct < 8; oct++) {
        const int buf = oct & 1;
        __syncthreads();
        if (oct + 1 < 8) preloadF(oct + 1);

        unsigned long long acc2[4] = {0ULL, 0ULL, 0ULL, 0ULL};
#pragma unroll
        for (int dy = 0; dy < KK; dy++) {
#pragma unroll
            for (int dx = 0; dx < KK; dx++) {
                unsigned long long kd = dup2(kl[dy*KK + dx]);
                const unsigned long long* q =
                    (const unsigned long long*)&s_f[buf][((ty + dy)*22 + tx + dx)*10];
                fma2(acc2[0], q[0], kd);
                fma2(acc2[1], q[1], kd);
                fma2(acc2[2], q[2], kd);
                fma2(acc2[3], q[3], kd);
            }
        }

        if (oct + 1 < 8) storeF(buf ^ 1);

#pragma unroll
        for (int j = 0; j < 4; j++) {
            float2 f = unpack2(acc2[j]);
            int off0 = (oct*8 + 2*j)*HWq + y*Wq + xx;
            ob[off0]       = xb[off0]       + f.x;
            ob[off0 + HWq] = xb[off0 + HWq] + f.y;
        }
    }
}

// ---------------------------------------------------------------------------
extern "C" void kernel_launch(void* const* d_in, const int* in_sizes, int n_in,
                              void* d_out, int out_size)
{
    const float* x   = (const float*)d_in[0];
    const float* kf  = (const float*)d_in[1];
    const float* fw1 = (const float*)d_in[2];
    const float* fb1 = (const float*)d_in[3];
    const float* fw2 = (const float*)d_in[4];
    const float* fb2 = (const float*)d_in[5];
    const float* mw1 = (const float*)d_in[6];
    const float* mb1 = (const float*)d_in[7];
    const float* mw2 = (const float*)d_in[8];
    const float* mb2 = (const float*)d_in[9];
    const float* lw1 = (const float*)d_in[10];
    const float* lb1 = (const float*)d_in[11];
    const float* lw2 = (const float*)d_in[12];
    const float* lb2 = (const float*)d_in[13];
    float* out = (float*)d_out;

    float *rxp, *kfp, *b1fp, *b1mp, *b2fp, *b2mp, *lpp;
    float2 *wBp, *wL1p, *wL2p;
    cudaGetSymbolAddress((void**)&rxp,  g_rx);
    cudaGetSymbolAddress((void**)&kfp,  g_kf);
    cudaGetSymbolAddress((void**)&b1fp, g_b1f);
    cudaGetSymbolAddress((void**)&b1mp, g_b1m);
    cudaGetSymbolAddress((void**)&b2fp, g_b2f);
    cudaGetSymbolAddress((void**)&b2mp, g_b2m);
    cudaGetSymbolAddress((void**)&lpp,  g_lp);
    cudaGetSymbolAddress((void**)&wBp,  g_wB2);
    cudaGetSymbolAddress((void**)&wL1p, g_wL1);
    cudaGetSymbolAddress((void**)&wL2p, g_wL2);

    dim3 cblk(256);
    prep_in_kernel<<<dim3((Bq*8*HWq)/256, 2), cblk>>>(x, kf, rxp, kfp);
    prep_wt_all_kernel<<<(4*WB2_CONV + 3840)/256 + 1, cblk>>>(
        fw1, fw2, mw1, mw2, lw1, lw2, wBp, wL1p, wL2p);

    lp_mma_kernel<<<dim3(Hq, Bq), 128>>>(kfp, wL1p, wL2p, lb1, lb2, lpp);

    dim3 tgrid(Hq, 2*Bq);   // 1024 CTAs per stage
    dim3 tblk(128);
    const float2* wf1 = wBp + 0*WB2_CONV;
    const float2* wf2 = wBp + 1*WB2_CONV;
    const float2* wm1 = wBp + 2*WB2_CONV;
    const float2* wm2 = wBp + 3*WB2_CONV;

    conv_mma_kernel<true ><<<tgrid, tblk>>>(
        rxp, kfp, wf1, wm1, fb1, mb1, b1fp, b1mp);
    conv_mma_kernel<false><<<tgrid, tblk>>>(
        b1fp, b1mp, wf2, wm2, fb2, mb2, b2fp, b2mp);

    dim3 lgrid(Wq/TILE, Hq/TILE, Bq);
    local_conv_kernel<<<lgrid, cblk>>>(x, b2fp, b2mp, lpp, out);
}

// round 15
// speedup vs baseline: 1.8474x; 1.8474x over previous
#include <cuda_runtime.h>
#include <cstdint>

#define Bq 4
#define Cq 64
#define Hq 128
#define Wq 128
#define HWq (Hq*Wq)
#define CHWq (Cq*HWq)
#define HW8 (HWq*8)
#define KK 7
#define TAPS 49
#define NGRP 24
#define NKB  72
#define WB2_CONV (NKB*256)

// scratch (allocation-free rule: __device__ globals). NHWC8 for intermediates.
__device__ float  g_rx [Bq*CHWq];
__device__ float  g_kf [Bq*CHWq];
__device__ float  g_b1f[Bq*CHWq];
__device__ float  g_b1m[Bq*CHWq];
__device__ float  g_b2f[Bq*CHWq];
__device__ float  g_b2m[Bq*CHWq];
__device__ float  g_lp [Bq*HWq*52];     // [b][hw][52] tap-innermost
__device__ float2 g_wB2[4*WB2_CONV];
__device__ float2 g_wL1[2048];
__device__ float2 g_wL2[1792];

// ---------------------------------------------------------------------------
__device__ __forceinline__ uint32_t tf32_hi(float v) {
    uint32_t r; asm("cvt.rna.tf32.f32 %0, %1;" : "=r"(r) : "f"(v)); return r;
}
__device__ __forceinline__ float tf32f(float v) {
    return __uint_as_float(tf32_hi(v));
}
__device__ __forceinline__ void cp16(void* dst, const void* src) {
    unsigned d = (unsigned)__cvta_generic_to_shared(dst);
    asm volatile("cp.async.ca.shared.global [%0], [%1], 16;" :: "r"(d), "l"(src));
}
#define CP_COMMIT asm volatile("cp.async.commit_group;")
#define CP_WAIT0  asm volatile("cp.async.wait_group 0;")

__device__ __forceinline__ void mma_tf32(float d[4], const uint32_t a[4],
                                         uint32_t b0, uint32_t b1)
{
    asm volatile(
        "mma.sync.aligned.m16n8k8.row.col.f32.tf32.tf32.f32 "
        "{%0,%1,%2,%3}, {%4,%5,%6,%7}, {%8,%9}, {%0,%1,%2,%3};"
        : "+f"(d[0]), "+f"(d[1]), "+f"(d[2]), "+f"(d[3])
        : "r"(a[0]), "r"(a[1]), "r"(a[2]), "r"(a[3]), "r"(b0), "r"(b1));
}
__device__ __forceinline__ unsigned long long dup2(float a) {
    unsigned long long r;
    asm("mov.b64 %0, {%1, %1};" : "=l"(r) : "f"(a)); return r;
}
__device__ __forceinline__ void fma2(unsigned long long& d,
                                     unsigned long long a, unsigned long long b) {
    asm("fma.rn.f32x2 %0, %1, %2, %0;" : "+l"(d) : "l"(a), "l"(b));
}
__device__ __forceinline__ float2 unpack2(unsigned long long v) {
    float2 f;
    asm("mov.b64 {%0, %1}, %2;" : "=f"(f.x), "=f"(f.y) : "l"(v)); return f;
}

// ---------------------------------------------------------------------------
// prep: both NCHW -> NHWC8 transposes in one launch (grid.y selects tensor)
// ---------------------------------------------------------------------------
__global__ void prep_in_kernel(const float* __restrict__ x, const float* __restrict__ kf,
                               float* __restrict__ rx, float* __restrict__ kfo)
{
    int i  = blockIdx.x*256 + threadIdx.x;
    bool second = (blockIdx.y != 0);
    const float* in  = second ? kf  : x;
    float*       out = second ? kfo : rx;
    int hw = i & (HWq-1);
    int bo = i >> 14;
    const float* p = in + bo*8*HWq + hw;
    float v[8];
#pragma unroll
    for (int c = 0; c < 8; c++) {
        float t = p[c*HWq];
        v[c] = second ? t : fmaxf(t, 0.f);
    }
    float4* o = (float4*)(out + (size_t)i*8);
    o[0] = make_float4(v[0], v[1], v[2], v[3]);
    o[1] = make_float4(v[4], v[5], v[6], v[7]);
}

// all weight packing in one launch: conv frags then lp frags
__global__ void prep_wt_all_kernel(
    const float* __restrict__ w0, const float* __restrict__ w1,
    const float* __restrict__ w2, const float* __restrict__ w3,
    const float* __restrict__ lw1, const float* __restrict__ lw2,
    float2* __restrict__ wB2, float2* __restrict__ wL1, float2* __restrict__ wL2)
{
    int i = blockIdx.x*256 + threadIdx.x;
    if (i < 4*WB2_CONV) {
        int conv = i / WB2_CONV;
        int r    = i - conv*WB2_CONV;
        int kb   = r >> 8;
        int r2   = r & 255;
        int nb   = r2 >> 5;
        int lane = r2 & 31;
        int g  = kb / 3, dx = kb - g*3;
        int dy = g >> 3, oct = g & 7;
        int tap = dy*3 + dx;
        int n   = nb*8 + (lane >> 2);
        int ci0 = oct*8 + (lane & 3);
        const float* w = (conv == 0) ? w0 : (conv == 1) ? w1 : (conv == 2) ? w2 : w3;
        float v0 = w[(n*Cq + ci0    )*9 + tap];
        float v1 = w[(n*Cq + ci0 + 4)*9 + tap];
        wB2[i] = make_float2(tf32f(v0), tf32f(v1));
    } else {
        int j = i - 4*WB2_CONV;
        if (j < 2048) {
            int kb = j >> 8, r2 = j & 255, nb = r2 >> 5, lane = r2 & 31;
            int n = nb*8 + (lane >> 2), ci = kb*8 + (lane & 3);
            wL1[j] = make_float2(tf32f(lw1[n*64 + ci]), tf32f(lw1[n*64 + ci + 4]));
        } else if (j < 3840) {
            int q = j - 2048;
            int kb = q / 224, r2 = q - kb*224, nb = r2 >> 5, lane = r2 & 31;
            int n = nb*8 + (lane >> 2), ci = kb*8 + (lane & 3);
            float v0 = (n < 49) ? lw2[n*64 + ci]     : 0.f;
            float v1 = (n < 49) ? lw2[n*64 + ci + 4] : 0.f;
            wL2[q] = make_float2(tf32f(v0), tf32f(v1));
        }
    }
}

// ---------------------------------------------------------------------------
// conv3x3 via mma.sync tf32 1-pass. NHWC8 in/out. EXACT R12 configuration:
// 128 threads, 1 row/CTA, grid (Hq, 2*Bq), launch_bounds(128,4), TWO
// __syncthreads per group (keeps warps convoyed; R14 showed removing the
// bottom barrier + higher occ trashes L1 -> 3x L2 traffic).
// ---------------------------------------------------------------------------
template<bool RELU_OUT>
__global__ __launch_bounds__(128, 4)
void conv_mma_kernel(const float* __restrict__ inA, const float* __restrict__ inB,
                     const float2* __restrict__ wBA, const float2* __restrict__ wBB,
                     const float* __restrict__ biasA, const float* __restrict__ biasB,
                     float* __restrict__ outA, float* __restrict__ outB)
{
    __shared__ alignas(16) float  sA[2][130*8];
    __shared__ alignas(16) float2 sB[2][768];

    const int y  = blockIdx.x;
    const int z  = blockIdx.y;
    const int b  = z & 3;
    const bool pB = (z >= 4);
    const float*  in   = (pB ? inB  : inA) + b*CHWq;
    const float2* wB   =  pB ? wBB  : wBA;
    const float*  bias =  pB ? biasB : biasA;
    float*        out  = (pB ? outB : outA) + b*CHWq;

    const int tid  = threadIdx.x;
    const int wid  = tid >> 5;
    const int lane = tid & 31;

    if (tid < 32) {
        int bb = tid >> 4, rr = (tid >> 3) & 1, cc = tid & 7;
        sA[bb][(rr ? 129*8 : 0) + cc] = 0.f;
    }

    float d[2][8][4];
#pragma unroll
    for (int mi = 0; mi < 2; mi++)
#pragma unroll
        for (int ni = 0; ni < 8; ni++)
#pragma unroll
            for (int r = 0; r < 4; r++) d[mi][ni][r] = 0.f;

    float4 va, vb_;
    auto preloadA = [&](int g) {
        int dy = g >> 3, oct = g & 7;
        int yin = y + dy - 1;
        if (yin >= 0 && yin < Hq) {
            const float4* p = (const float4*)(in + oct*HW8 + (yin*Wq + tid)*8);
            va  = __ldg(p);
            vb_ = __ldg(p + 1);
        } else {
            va  = make_float4(0.f, 0.f, 0.f, 0.f);
            vb_ = make_float4(0.f, 0.f, 0.f, 0.f);
        }
    };
    auto storeA = [&](int buf) {
        int px = tid + 1;
        int sw = (px >> 2) & 1;
        float* base = &sA[buf][px*8];
        float4 p0 = make_float4(tf32f(va.x), tf32f(vb_.x), tf32f(va.y), tf32f(vb_.y));
        float4 p1 = make_float4(tf32f(va.z), tf32f(vb_.z), tf32f(va.w), tf32f(vb_.w));
        *(float4*)(base + ((0 ^ sw) << 2)) = p0;
        *(float4*)(base + ((1 ^ sw) << 2)) = p1;
    };
    auto stageB = [&](int buf, int g) {
        const float4* src = (const float4*)(wB + g*768);
        float4* dst = (float4*)sB[buf];
        cp16(dst + tid,       src + tid);
        cp16(dst + 128 + tid, src + 128 + tid);
        cp16(dst + 256 + tid, src + 256 + tid);
        CP_COMMIT;
    };

    preloadA(0);
    storeA(0);
    stageB(0, 0);

    for (int g = 0; g < NGRP; g++) {
        const int buf = g & 1;
        CP_WAIT0;
        __syncthreads();
        if (g + 1 < NGRP) { stageB(buf ^ 1, g + 1); preloadA(g + 1); }

#pragma unroll
        for (int dx = 0; dx < 3; dx++) {
            uint32_t a[2][4];
#pragma unroll
            for (int mi = 0; mi < 2; mi++) {
                int pxl = wid*32 + mi*16 + (lane >> 2) + dx;
                int c   = lane & 3;
                int sw  = (pxl >> 2) & 1;
                int off = (((c >> 1) ^ sw) << 2) + ((c & 1) << 1);
                float2 q0 = *(float2*)&sA[buf][pxl*8 + off];
                float2 q1 = *(float2*)&sA[buf][(pxl + 8)*8 + off];
                a[mi][0] = __float_as_uint(q0.x);
                a[mi][2] = __float_as_uint(q0.y);
                a[mi][1] = __float_as_uint(q1.x);
                a[mi][3] = __float_as_uint(q1.y);
            }
#pragma unroll
            for (int ni = 0; ni < 8; ni++) {
                float2 bq = sB[buf][(dx*8 + ni)*32 + lane];
                uint32_t b0 = __float_as_uint(bq.x), b1 = __float_as_uint(bq.y);
#pragma unroll
                for (int mi = 0; mi < 2; mi++)
                    mma_tf32(d[mi][ni], a[mi], b0, b1);
            }
        }

        if (g + 1 < NGRP) storeA(buf ^ 1);
        __syncthreads();
    }

    const int row  = lane >> 2;
    const int colb = (lane & 3) << 1;
#pragma unroll
    for (int mi = 0; mi < 2; mi++) {
        int px0 = wid*32 + mi*16 + row;
#pragma unroll
        for (int ni = 0; ni < 8; ni++) {
            float b0 = __ldg(bias + ni*8 + colb);
            float b1 = __ldg(bias + ni*8 + colb + 1);
            float2 r0 = make_float2(d[mi][ni][0] + b0, d[mi][ni][1] + b1);
            float2 r1 = make_float2(d[mi][ni][2] + b0, d[mi][ni][3] + b1);
            if (RELU_OUT) {
                r0.x = fmaxf(r0.x, 0.f); r0.y = fmaxf(r0.y, 0.f);
                r1.x = fmaxf(r1.x, 0.f); r1.y = fmaxf(r1.y, 0.f);
            }
            float* o8 = out + ni*HW8;
            *(float2*)(o8 + (y*Wq + px0    )*8 + colb) = r0;
            *(float2*)(o8 + (y*Wq + px0 + 8)*8 + colb) = r1;
        }
    }
}

// ---------------------------------------------------------------------------
// lp path via mma.sync tf32 (unchanged)
// ---------------------------------------------------------------------------
__global__ __launch_bounds__(128, 3)
void lp_mma_kernel(const float* __restrict__ kf,
                   const float2* __restrict__ wL1, const float2* __restrict__ wL2,
                   const float* __restrict__ b1, const float* __restrict__ b2,
                   float* __restrict__ lp)
{
    __shared__ alignas(16) float sU[8192];
    __shared__ float s_b1[64];
    __shared__ float s_b2[56];

    const int y = blockIdx.x, b = blockIdx.y;
    const int tid = threadIdx.x, wid = tid >> 5, lane = tid & 31;
    const float* kfb = kf + b*CHWq;

    if (tid < 64) s_b1[tid] = b1[tid];
    if (tid < 56) s_b2[tid] = (tid < 49) ? b2[tid] : 0.f;

    {
        int px = tid, sw = (px >> 2) & 1;
#pragma unroll
        for (int oct = 0; oct < 8; oct++) {
            const float4* p = (const float4*)(kfb + oct*HW8 + (y*Wq + px)*8);
            float4 u0 = __ldg(p), u1 = __ldg(p + 1);
            float* base = &sU[oct*1024 + px*8];
            float4 p0 = make_float4(tf32f(u0.x), tf32f(u1.x), tf32f(u0.y), tf32f(u1.y));
            float4 p1 = make_float4(tf32f(u0.z), tf32f(u1.z), tf32f(u0.w), tf32f(u1.w));
            *(float4*)(base + ((0 ^ sw) << 2)) = p0;
            *(float4*)(base + ((1 ^ sw) << 2)) = p1;
        }
    }
    __syncthreads();

    float d1[2][8][4];
#pragma unroll
    for (int mi = 0; mi < 2; mi++)
#pragma unroll
        for (int ni = 0; ni < 8; ni++)
#pragma unroll
            for (int r = 0; r < 4; r++) d1[mi][ni][r] = 0.f;

#pragma unroll
    for (int oct = 0; oct < 8; oct++) {
        uint32_t a[2][4];
#pragma unroll
        for (int mi = 0; mi < 2; mi++) {
            int pxl = wid*32 + mi*16 + (lane >> 2);
            int c = lane & 3, sw = (pxl >> 2) & 1;
            int off = (((c >> 1) ^ sw) << 2) + ((c & 1) << 1);
            float2 q0 = *(float2*)&sU[oct*1024 + pxl*8 + off];
            float2 q1 = *(float2*)&sU[oct*1024 + (pxl + 8)*8 + off];
            a[mi][0] = __float_as_uint(q0.x);
            a[mi][2] = __float_as_uint(q0.y);
            a[mi][1] = __float_as_uint(q1.x);
            a[mi][3] = __float_as_uint(q1.y);
        }
#pragma unroll
        for (int ni = 0; ni < 8; ni++) {
            float2 bq = __ldg(&wL1[(oct*8 + ni)*32 + lane]);
            uint32_t b0 = __float_as_uint(bq.x), b1v = __float_as_uint(bq.y);
#pragma unroll
            for (int mi = 0; mi < 2; mi++)
                mma_tf32(d1[mi][ni], a[mi], b0, b1v);
        }
    }
    __syncthreads();

    {
        const int colb = (lane & 3) << 1;
#pragma unroll
        for (int mi = 0; mi < 2; mi++) {
            int row0 = wid*32 + mi*16 + (lane >> 2);
            int sw   = (row0 >> 2) & 1;
            int blk  = ((((colb & 3) >> 1) ^ sw) << 2);
            int posE = blk + (colb >= 4 ? 1 : 0);
            int posO = blk + 2 + (colb >= 4 ? 1 : 0);
#pragma unroll
            for (int ni = 0; ni < 8; ni++) {
                float bA = s_b1[ni*8 + colb], bB = s_b1[ni*8 + colb + 1];
                float* base = &sU[ni*1024];
                base[row0*8 + posE]       = tf32f(fmaxf(d1[mi][ni][0] + bA, 0.f));
                base[row0*8 + posO]       = tf32f(fmaxf(d1[mi][ni][1] + bB, 0.f));
                base[(row0 + 8)*8 + posE] = tf32f(fmaxf(d1[mi][ni][2] + bA, 0.f));
                base[(row0 + 8)*8 + posO] = tf32f(fmaxf(d1[mi][ni][3] + bB, 0.f));
            }
        }
    }
    __syncthreads();

    float d2[2][7][4];
#pragma unroll
    for (int mi = 0; mi < 2; mi++)
#pragma unroll
        for (int ni = 0; ni < 7; ni++)
#pragma unroll
            for (int r = 0; r < 4; r++) d2[mi][ni][r] = 0.f;

#pragma unroll
    for (int oct = 0; oct < 8; oct++) {
        uint32_t a[2][4];
#pragma unroll
        for (int mi = 0; mi < 2; mi++) {
            int pxl = wid*32 + mi*16 + (lane >> 2);
            int c = lane & 3, sw = (pxl >> 2) & 1;
            int off = (((c >> 1) ^ sw) << 2) + ((c & 1) << 1);
            float2 q0 = *(float2*)&sU[oct*1024 + pxl*8 + off];
            float2 q1 = *(float2*)&sU[oct*1024 + (pxl + 8)*8 + off];
            a[mi][0] = __float_as_uint(q0.x);
            a[mi][2] = __float_as_uint(q0.y);
            a[mi][1] = __float_as_uint(q1.x);
            a[mi][3] = __float_as_uint(q1.y);
        }
#pragma unroll
        for (int ni = 0; ni < 7; ni++) {
            float2 bq = __ldg(&wL2[(oct*7 + ni)*32 + lane]);
            uint32_t b0 = __float_as_uint(bq.x), b1v = __float_as_uint(bq.y);
#pragma unroll
            for (int mi = 0; mi < 2; mi++)
                mma_tf32(d2[mi][ni], a[mi], b0, b1v);
        }
    }

    const int colb = (lane & 3) << 1;
    float* lpb = lp + (size_t)(b*HWq + y*Wq)*52;
#pragma unroll
    for (int mi = 0; mi < 2; mi++) {
#pragma unroll
        for (int rh = 0; rh < 2; rh++) {
            int px = wid*32 + mi*16 + (lane >> 2) + rh*8;
            float v[7][2];
            float ls = 0.f;
#pragma unroll
            for (int ni = 0; ni < 7; ni++) {
                int col = ni*8 + colb;
                v[ni][0] = d2[mi][ni][rh*2 + 0] + s_b2[col];
                v[ni][1] = d2[mi][ni][rh*2 + 1] + s_b2[col + 1];
                ls += v[ni][0] + v[ni][1];
            }
            ls += __shfl_xor_sync(0xffffffff, ls, 1);
            ls += __shfl_xor_sync(0xffffffff, ls, 2);
            float m = ls * (1.0f/49.0f);
            float* rowp = lpb + (size_t)px*52;
#pragma unroll
            for (int ni = 0; ni < 7; ni++) {
                int col = ni*8 + colb;
                if (col < 52) {
                    float2 o = make_float2(v[ni][0] - m + (1.0f/49.0f),
                                           v[ni][1] - m + (1.0f/49.0f));
                    *(float2*)(rowp + col) = o;
                }
            }
        }
    }
}

// ---------------------------------------------------------------------------
// dynamic 7x7 local conv + residual; feat = fp*mp computed during staging.
// ---------------------------------------------------------------------------
#define TILE 16
__global__ __launch_bounds__(256, 2)
void local_conv_kernel(const float* __restrict__ x,
                       const float* __restrict__ fp, const float* __restrict__ mp,
                       const float* __restrict__ lp, float* __restrict__ out)
{
    __shared__ alignas(16) float s_f[2][22*22*10];
    const int b  = blockIdx.z;
    const int x0 = blockIdx.x * TILE;
    const int y0 = blockIdx.y * TILE;
    const int tid = threadIdx.x;
    const int tx = tid & 15, ty = tid >> 4;
    const int y = y0 + ty, xx = x0 + tx;

    float kl[TAPS];
    {
        const float4* klb = (const float4*)(lp + (size_t)(b*HWq + y*Wq + xx)*52);
        float4 t[13];
#pragma unroll
        for (int q = 0; q < 13; q++) t[q] = __ldg(klb + q);
#pragma unroll
        for (int k = 0; k < TAPS; k++) kl[k] = ((const float*)t)[k];
    }

    const float* fpb = fp + b*CHWq;
    const float* mpb = mp + b*CHWq;
    const float* xb  = x  + b*CHWq;
    float*       ob  = out + b*CHWq;

    float4 pv[2][2];
    auto preloadF = [&](int oct) {
#pragma unroll
        for (int s = 0; s < 2; s++) {
            int idx = tid + s*256;
            if (idx < 484) {
                int r  = idx / 22;
                int cc = idx - r*22;
                int gy = y0 + r - 3, gx = x0 + cc - 3;
                if (gy >= 0 && gy < Hq && gx >= 0 && gx < Wq) {
                    const float4* pf = (const float4*)(fpb + oct*HW8 + (gy*Wq + gx)*8);
                    const float4* pm = (const float4*)(mpb + oct*HW8 + (gy*Wq + gx)*8);
                    float4 a0 = __ldg(pf), a1 = __ldg(pf + 1);
                    float4 m0 = __ldg(pm), m1 = __ldg(pm + 1);
                    pv[s][0] = make_float4(a0.x*m0.x, a0.y*m0.y, a0.z*m0.z, a0.w*m0.w);
                    pv[s][1] = make_float4(a1.x*m1.x, a1.y*m1.y, a1.z*m1.z, a1.w*m1.w);
                } else {
                    pv[s][0] = make_float4(0.f, 0.f, 0.f, 0.f);
                    pv[s][1] = make_float4(0.f, 0.f, 0.f, 0.f);
                }
            }
        }
    };
    auto storeF = [&](int buf) {
#pragma unroll
        for (int s = 0; s < 2; s++) {
            int idx = tid + s*256;
            if (idx < 484) {
                float* dst = &s_f[buf][idx*10];
                *(float2*)(dst + 0) = make_float2(pv[s][0].x, pv[s][0].y);
                *(float2*)(dst + 2) = make_float2(pv[s][0].z, pv[s][0].w);
                *(float2*)(dst + 4) = make_float2(pv[s][1].x, pv[s][1].y);
                *(float2*)(dst + 6) = make_float2(pv[s][1].z, pv[s][1].w);
            }
        }
    };

    preloadF(0);
    storeF(0);

    for (int oct = 0; oct < 8; oct++) {
        const int buf = oct & 1;
        __syncthreads();
        if (oct + 1 < 8) preloadF(oct + 1);

        unsigned long long acc2[4] = {0ULL, 0ULL, 0ULL, 0ULL};
#pragma unroll
        for (int dy = 0; dy < KK; dy++) {
#pragma unroll
            for (int dx = 0; dx < KK; dx++) {
                unsigned long long kd = dup2(kl[dy*KK + dx]);
                const unsigned long long* q =
                    (const unsigned long long*)&s_f[buf][((ty + dy)*22 + tx + dx)*10];
                fma2(acc2[0], q[0], kd);
                fma2(acc2[1], q[1], kd);
                fma2(acc2[2], q[2], kd);
                fma2(acc2[3], q[3], kd);
            }
        }

        if (oct + 1 < 8) storeF(buf ^ 1);

#pragma unroll
        for (int j = 0; j < 4; j++) {
            float2 f = unpack2(acc2[j]);
            int off0 = (oct*8 + 2*j)*HWq + y*Wq + xx;
            ob[off0]       = xb[off0]       + f.x;
            ob[off0 + HWq] = xb[off0 + HWq] + f.y;
        }
    }
}

// ---------------------------------------------------------------------------
extern "C" void kernel_launch(void* const* d_in, const int* in_sizes, int n_in,
                              void* d_out, int out_size)
{
    const float* x   = (const float*)d_in[0];
    const float* kf  = (const float*)d_in[1];
    const float* fw1 = (const float*)d_in[2];
    const float* fb1 = (const float*)d_in[3];
    const float* fw2 = (const float*)d_in[4];
    const float* fb2 = (const float*)d_in[5];
    const float* mw1 = (const float*)d_in[6];
    const float* mb1 = (const float*)d_in[7];
    const float* mw2 = (const float*)d_in[8];
    const float* mb2 = (const float*)d_in[9];
    const float* lw1 = (const float*)d_in[10];
    const float* lb1 = (const float*)d_in[11];
    const float* lw2 = (const float*)d_in[12];
    const float* lb2 = (const float*)d_in[13];
    float* out = (float*)d_out;

    float *rxp, *kfp, *b1fp, *b1mp, *b2fp, *b2mp, *lpp;
    float2 *wBp, *wL1p, *wL2p;
    cudaGetSymbolAddress((void**)&rxp,  g_rx);
    cudaGetSymbolAddress((void**)&kfp,  g_kf);
    cudaGetSymbolAddress((void**)&b1fp, g_b1f);
    cudaGetSymbolAddress((void**)&b1mp, g_b1m);
    cudaGetSymbolAddress((void**)&b2fp, g_b2f);
    cudaGetSymbolAddress((void**)&b2mp, g_b2m);
    cudaGetSymbolAddress((void**)&lpp,  g_lp);
    cudaGetSymbolAddress((void**)&wBp,  g_wB2);
    cudaGetSymbolAddress((void**)&wL1p, g_wL1);
    cudaGetSymbolAddress((void**)&wL2p, g_wL2);

    dim3 cblk(256);
    prep_in_kernel<<<dim3((Bq*8*HWq)/256, 2), cblk>>>(x, kf, rxp, kfp);
    prep_wt_all_kernel<<<(4*WB2_CONV + 3840)/256 + 1, cblk>>>(
        fw1, fw2, mw1, mw2, lw1, lw2, wBp, wL1p, wL2p);

    lp_mma_kernel<<<dim3(Hq, Bq), 128>>>(kfp, wL1p, wL2p, lb1, lb2, lpp);

    dim3 tgrid(Hq, 2*Bq);   // 1024 CTAs per stage
    dim3 tblk(128);
    const float2* wf1 = wBp + 0*WB2_CONV;
    const float2* wf2 = wBp + 1*WB2_CONV;
    const float2* wm1 = wBp + 2*WB2_CONV;
    const float2* wm2 = wBp + 3*WB2_CONV;

    conv_mma_kernel<true ><<<tgrid, tblk>>>(
        rxp, kfp, wf1, wm1, fb1, mb1, b1fp, b1mp);
    conv_mma_kernel<false><<<tgrid, tblk>>>(
        b1fp, b1mp, wf2, wm2, fb2, mb2, b2fp, b2mp);

    dim3 lgrid(Wq/TILE, Hq/TILE, Bq);
    local_conv_kernel<<<lgrid, cblk>>>(x, b2fp, b2mp, lpp, out);
}

// round 16
// speedup vs baseline: 1.8755x; 1.0152x over previous
#include <cuda_runtime.h>
#include <cstdint>

#define Bq 4
#define Cq 64
#define Hq 128
#define Wq 128
#define HWq (Hq*Wq)
#define CHWq (Cq*HWq)
#define HW8 (HWq*8)
#define KK 7
#define TAPS 49
#define NGRP 24
#define NKB  72
#define WB2_CONV (NKB*256)

// scratch (allocation-free rule: __device__ globals). NHWC8 for intermediates.
__device__ float  g_b1f[Bq*CHWq];
__device__ float  g_b1m[Bq*CHWq];
__device__ float  g_b2f[Bq*CHWq];
__device__ float  g_b2m[Bq*CHWq];
__device__ float  g_lp [Bq*HWq*52];     // [b][hw][52] tap-innermost
__device__ float2 g_wB2[4*WB2_CONV];
__device__ float2 g_wL1[2048];
__device__ float2 g_wL2[1792];

// ---------------------------------------------------------------------------
__device__ __forceinline__ uint32_t tf32_hi(float v) {
    uint32_t r; asm("cvt.rna.tf32.f32 %0, %1;" : "=r"(r) : "f"(v)); return r;
}
__device__ __forceinline__ float tf32f(float v) {
    return __uint_as_float(tf32_hi(v));
}
__device__ __forceinline__ void cp16(void* dst, const void* src) {
    unsigned d = (unsigned)__cvta_generic_to_shared(dst);
    asm volatile("cp.async.ca.shared.global [%0], [%1], 16;" :: "r"(d), "l"(src));
}
#define CP_COMMIT asm volatile("cp.async.commit_group;")
#define CP_WAIT0  asm volatile("cp.async.wait_group 0;")

__device__ __forceinline__ void mma_tf32(float d[4], const uint32_t a[4],
                                         uint32_t b0, uint32_t b1)
{
    asm volatile(
        "mma.sync.aligned.m16n8k8.row.col.f32.tf32.tf32.f32 "
        "{%0,%1,%2,%3}, {%4,%5,%6,%7}, {%8,%9}, {%0,%1,%2,%3};"
        : "+f"(d[0]), "+f"(d[1]), "+f"(d[2]), "+f"(d[3])
        : "r"(a[0]), "r"(a[1]), "r"(a[2]), "r"(a[3]), "r"(b0), "r"(b1));
}
__device__ __forceinline__ unsigned long long dup2(float a) {
    unsigned long long r;
    asm("mov.b64 %0, {%1, %1};" : "=l"(r) : "f"(a)); return r;
}
__device__ __forceinline__ void fma2(unsigned long long& d,
                                     unsigned long long a, unsigned long long b) {
    asm("fma.rn.f32x2 %0, %1, %2, %0;" : "+l"(d) : "l"(a), "l"(b));
}
__device__ __forceinline__ float2 unpack2(unsigned long long v) {
    float2 f;
    asm("mov.b64 {%0, %1}, %2;" : "=f"(f.x), "=f"(f.y) : "l"(v)); return f;
}

// ---------------------------------------------------------------------------
// all weight packing in one launch: conv frags then lp frags
// ---------------------------------------------------------------------------
__global__ void prep_wt_all_kernel(
    const float* __restrict__ w0, const float* __restrict__ w1,
    const float* __restrict__ w2, const float* __restrict__ w3,
    const float* __restrict__ lw1, const float* __restrict__ lw2,
    float2* __restrict__ wB2, float2* __restrict__ wL1, float2* __restrict__ wL2)
{
    int i = blockIdx.x*256 + threadIdx.x;
    if (i < 4*WB2_CONV) {
        int conv = i / WB2_CONV;
        int r    = i - conv*WB2_CONV;
        int kb   = r >> 8;
        int r2   = r & 255;
        int nb   = r2 >> 5;
        int lane = r2 & 31;
        int g  = kb / 3, dx = kb - g*3;
        int dy = g >> 3, oct = g & 7;
        int tap = dy*3 + dx;
        int n   = nb*8 + (lane >> 2);
        int ci0 = oct*8 + (lane & 3);
        const float* w = (conv == 0) ? w0 : (conv == 1) ? w1 : (conv == 2) ? w2 : w3;
        float v0 = w[(n*Cq + ci0    )*9 + tap];
        float v1 = w[(n*Cq + ci0 + 4)*9 + tap];
        wB2[i] = make_float2(tf32f(v0), tf32f(v1));
    } else {
        int j = i - 4*WB2_CONV;
        if (j < 2048) {
            int kb = j >> 8, r2 = j & 255, nb = r2 >> 5, lane = r2 & 31;
            int n = nb*8 + (lane >> 2), ci = kb*8 + (lane & 3);
            wL1[j] = make_float2(tf32f(lw1[n*64 + ci]), tf32f(lw1[n*64 + ci + 4]));
        } else if (j < 3840) {
            int q = j - 2048;
            int kb = q / 224, r2 = q - kb*224, nb = r2 >> 5, lane = r2 & 31;
            int n = nb*8 + (lane >> 2), ci = kb*8 + (lane & 3);
            float v0 = (n < 49) ? lw2[n*64 + ci]     : 0.f;
            float v1 = (n < 49) ? lw2[n*64 + ci + 4] : 0.f;
            wL2[q] = make_float2(tf32f(v0), tf32f(v1));
        }
    }
}

// ---------------------------------------------------------------------------
// conv3x3 via mma.sync tf32 1-pass. R12 configuration (128 thr, 1 row/CTA,
// occ 4, two barriers per group). RAW_IN=true: inputs are NCHW, path A gets
// relu fused into the load (stage 1, reading x / kf directly). RAW_IN=false:
// inputs NHWC8 (stage 2). Output always NHWC8.
// ---------------------------------------------------------------------------
template<bool RAW_IN, bool RELU_OUT>
__global__ __launch_bounds__(128, 4)
void conv_mma_kernel(const float* __restrict__ inA, const float* __restrict__ inB,
                     const float2* __restrict__ wBA, const float2* __restrict__ wBB,
                     const float* __restrict__ biasA, const float* __restrict__ biasB,
                     float* __restrict__ outA, float* __restrict__ outB)
{
    __shared__ alignas(16) float  sA[2][130*8];
    __shared__ alignas(16) float2 sB[2][768];

    const int y  = blockIdx.x;
    const int z  = blockIdx.y;
    const int b  = z & 3;
    const bool pB = (z >= 4);
    const float*  in   = (pB ? inB  : inA) + b*CHWq;
    const float2* wB   =  pB ? wBB  : wBA;
    const float*  bias =  pB ? biasB : biasA;
    float*        out  = (pB ? outB : outA) + b*CHWq;

    const int tid  = threadIdx.x;
    const int wid  = tid >> 5;
    const int lane = tid & 31;

    if (tid < 32) {
        int bb = tid >> 4, rr = (tid >> 3) & 1, cc = tid & 7;
        sA[bb][(rr ? 129*8 : 0) + cc] = 0.f;
    }

    float d[2][8][4];
#pragma unroll
    for (int mi = 0; mi < 2; mi++)
#pragma unroll
        for (int ni = 0; ni < 8; ni++)
#pragma unroll
            for (int r = 0; r < 4; r++) d[mi][ni][r] = 0.f;

    float v[8];
    auto preloadA = [&](int g) {
        int dy = g >> 3, oct = g & 7;
        int yin = y + dy - 1;
        if (yin >= 0 && yin < Hq) {
            if (RAW_IN) {
                // NCHW: 8 strided LDG.32, coalesced across threads (tid = px)
                const float* p = in + oct*8*HWq + yin*Wq + tid;
#pragma unroll
                for (int i = 0; i < 8; i++) {
                    float t = __ldg(p + i*HWq);
                    v[i] = pB ? t : fmaxf(t, 0.f);   // relu(x) on path A only
                }
            } else {
                const float4* p = (const float4*)(in + oct*HW8 + (yin*Wq + tid)*8);
                float4 a0 = __ldg(p), a1 = __ldg(p + 1);
                v[0] = a0.x; v[1] = a0.y; v[2] = a0.z; v[3] = a0.w;
                v[4] = a1.x; v[5] = a1.y; v[6] = a1.z; v[7] = a1.w;
            }
        } else {
#pragma unroll
            for (int i = 0; i < 8; i++) v[i] = 0.f;
        }
    };
    auto storeA = [&](int buf) {
        int px = tid + 1;
        int sw = (px >> 2) & 1;
        float* base = &sA[buf][px*8];
        float4 p0 = make_float4(tf32f(v[0]), tf32f(v[4]), tf32f(v[1]), tf32f(v[5]));
        float4 p1 = make_float4(tf32f(v[2]), tf32f(v[6]), tf32f(v[3]), tf32f(v[7]));
        *(float4*)(base + ((0 ^ sw) << 2)) = p0;
        *(float4*)(base + ((1 ^ sw) << 2)) = p1;
    };
    auto stageB = [&](int buf, int g) {
        const float4* src = (const float4*)(wB + g*768);
        float4* dst = (float4*)sB[buf];
        cp16(dst + tid,       src + tid);
        cp16(dst + 128 + tid, src + 128 + tid);
        cp16(dst + 256 + tid, src + 256 + tid);
        CP_COMMIT;
    };

    preloadA(0);
    storeA(0);
    stageB(0, 0);

    for (int g = 0; g < NGRP; g++) {
        const int buf = g & 1;
        CP_WAIT0;
        __syncthreads();
        if (g + 1 < NGRP) { stageB(buf ^ 1, g + 1); preloadA(g + 1); }

#pragma unroll
        for (int dx = 0; dx < 3; dx++) {
            uint32_t a[2][4];
#pragma unroll
            for (int mi = 0; mi < 2; mi++) {
                int pxl = wid*32 + mi*16 + (lane >> 2) + dx;
                int c   = lane & 3;
                int sw  = (pxl >> 2) & 1;
                int off = (((c >> 1) ^ sw) << 2) + ((c & 1) << 1);
                float2 q0 = *(float2*)&sA[buf][pxl*8 + off];
                float2 q1 = *(float2*)&sA[buf][(pxl + 8)*8 + off];
                a[mi][0] = __float_as_uint(q0.x);
                a[mi][2] = __float_as_uint(q0.y);
                a[mi][1] = __float_as_uint(q1.x);
                a[mi][3] = __float_as_uint(q1.y);
            }
#pragma unroll
            for (int ni = 0; ni < 8; ni++) {
                float2 bq = sB[buf][(dx*8 + ni)*32 + lane];
                uint32_t b0 = __float_as_uint(bq.x), b1 = __float_as_uint(bq.y);
#pragma unroll
                for (int mi = 0; mi < 2; mi++)
                    mma_tf32(d[mi][ni], a[mi], b0, b1);
            }
        }

        if (g + 1 < NGRP) storeA(buf ^ 1);
        __syncthreads();
    }

    const int row  = lane >> 2;
    const int colb = (lane & 3) << 1;
#pragma unroll
    for (int mi = 0; mi < 2; mi++) {
        int px0 = wid*32 + mi*16 + row;
#pragma unroll
        for (int ni = 0; ni < 8; ni++) {
            float b0 = __ldg(bias + ni*8 + colb);
            float b1 = __ldg(bias + ni*8 + colb + 1);
            float2 r0 = make_float2(d[mi][ni][0] + b0, d[mi][ni][1] + b1);
            float2 r1 = make_float2(d[mi][ni][2] + b0, d[mi][ni][3] + b1);
            if (RELU_OUT) {
                r0.x = fmaxf(r0.x, 0.f); r0.y = fmaxf(r0.y, 0.f);
                r1.x = fmaxf(r1.x, 0.f); r1.y = fmaxf(r1.y, 0.f);
            }
            float* o8 = out + ni*HW8;
            *(float2*)(o8 + (y*Wq + px0    )*8 + colb) = r0;
            *(float2*)(o8 + (y*Wq + px0 + 8)*8 + colb) = r1;
        }
    }
}

// ---------------------------------------------------------------------------
// lp path via mma.sync tf32; kf read directly from NCHW.
// ---------------------------------------------------------------------------
__global__ __launch_bounds__(128, 3)
void lp_mma_kernel(const float* __restrict__ kf,
                   const float2* __restrict__ wL1, const float2* __restrict__ wL2,
                   const float* __restrict__ b1, const float* __restrict__ b2,
                   float* __restrict__ lp)
{
    __shared__ alignas(16) float sU[8192];
    __shared__ float s_b1[64];
    __shared__ float s_b2[56];

    const int y = blockIdx.x, b = blockIdx.y;
    const int tid = threadIdx.x, wid = tid >> 5, lane = tid & 31;
    const float* kfb = kf + b*CHWq;

    if (tid < 64) s_b1[tid] = b1[tid];
    if (tid < 56) s_b2[tid] = (tid < 49) ? b2[tid] : 0.f;

    {
        int px = tid, sw = (px >> 2) & 1;
#pragma unroll
        for (int oct = 0; oct < 8; oct++) {
            const float* p = kfb + oct*8*HWq + y*Wq + px;
            float u[8];
#pragma unroll
            for (int i = 0; i < 8; i++) u[i] = __ldg(p + i*HWq);
            float* base = &sU[oct*1024 + px*8];
            float4 p0 = make_float4(tf32f(u[0]), tf32f(u[4]), tf32f(u[1]), tf32f(u[5]));
            float4 p1 = make_float4(tf32f(u[2]), tf32f(u[6]), tf32f(u[3]), tf32f(u[7]));
            *(float4*)(base + ((0 ^ sw) << 2)) = p0;
            *(float4*)(base + ((1 ^ sw) << 2)) = p1;
        }
    }
    __syncthreads();

    float d1[2][8][4];
#pragma unroll
    for (int mi = 0; mi < 2; mi++)
#pragma unroll
        for (int ni = 0; ni < 8; ni++)
#pragma unroll
            for (int r = 0; r < 4; r++) d1[mi][ni][r] = 0.f;

#pragma unroll
    for (int oct = 0; oct < 8; oct++) {
        uint32_t a[2][4];
#pragma unroll
        for (int mi = 0; mi < 2; mi++) {
            int pxl = wid*32 + mi*16 + (lane >> 2);
            int c = lane & 3, sw = (pxl >> 2) & 1;
            int off = (((c >> 1) ^ sw) << 2) + ((c & 1) << 1);
            float2 q0 = *(float2*)&sU[oct*1024 + pxl*8 + off];
            float2 q1 = *(float2*)&sU[oct*1024 + (pxl + 8)*8 + off];
            a[mi][0] = __float_as_uint(q0.x);
            a[mi][2] = __float_as_uint(q0.y);
            a[mi][1] = __float_as_uint(q1.x);
            a[mi][3] = __float_as_uint(q1.y);
        }
#pragma unroll
        for (int ni = 0; ni < 8; ni++) {
            float2 bq = __ldg(&wL1[(oct*8 + ni)*32 + lane]);
            uint32_t b0 = __float_as_uint(bq.x), b1v = __float_as_uint(bq.y);
#pragma unroll
            for (int mi = 0; mi < 2; mi++)
                mma_tf32(d1[mi][ni], a[mi], b0, b1v);
        }
    }
    __syncthreads();

    {
        const int colb = (lane & 3) << 1;
#pragma unroll
        for (int mi = 0; mi < 2; mi++) {
            int row0 = wid*32 + mi*16 + (lane >> 2);
            int sw   = (row0 >> 2) & 1;
            int blk  = ((((colb & 3) >> 1) ^ sw) << 2);
            int posE = blk + (colb >= 4 ? 1 : 0);
            int posO = blk + 2 + (colb >= 4 ? 1 : 0);
#pragma unroll
            for (int ni = 0; ni < 8; ni++) {
                float bA = s_b1[ni*8 + colb], bB = s_b1[ni*8 + colb + 1];
                float* base = &sU[ni*1024];
                base[row0*8 + posE]       = tf32f(fmaxf(d1[mi][ni][0] + bA, 0.f));
                base[row0*8 + posO]       = tf32f(fmaxf(d1[mi][ni][1] + bB, 0.f));
                base[(row0 + 8)*8 + posE] = tf32f(fmaxf(d1[mi][ni][2] + bA, 0.f));
                base[(row0 + 8)*8 + posO] = tf32f(fmaxf(d1[mi][ni][3] + bB, 0.f));
            }
        }
    }
    __syncthreads();

    float d2[2][7][4];
#pragma unroll
    for (int mi = 0; mi < 2; mi++)
#pragma unroll
        for (int ni = 0; ni < 7; ni++)
#pragma unroll
            for (int r = 0; r < 4; r++) d2[mi][ni][r] = 0.f;

#pragma unroll
    for (int oct = 0; oct < 8; oct++) {
        uint32_t a[2][4];
#pragma unroll
        for (int mi = 0; mi < 2; mi++) {
            int pxl = wid*32 + mi*16 + (lane >> 2);
            int c = lane & 3, sw = (pxl >> 2) & 1;
            int off = (((c >> 1) ^ sw) << 2) + ((c & 1) << 1);
            float2 q0 = *(float2*)&sU[oct*1024 + pxl*8 + off];
            float2 q1 = *(float2*)&sU[oct*1024 + (pxl + 8)*8 + off];
            a[mi][0] = __float_as_uint(q0.x);
            a[mi][2] = __float_as_uint(q0.y);
            a[mi][1] = __float_as_uint(q1.x);
            a[mi][3] = __float_as_uint(q1.y);
        }
#pragma unroll
        for (int ni = 0; ni < 7; ni++) {
            float2 bq = __ldg(&wL2[(oct*7 + ni)*32 + lane]);
            uint32_t b0 = __float_as_uint(bq.x), b1v = __float_as_uint(bq.y);
#pragma unroll
            for (int mi = 0; mi < 2; mi++)
                mma_tf32(d2[mi][ni], a[mi], b0, b1v);
        }
    }

    const int colb = (lane & 3) << 1;
    float* lpb = lp + (size_t)(b*HWq + y*Wq)*52;
#pragma unroll
    for (int mi = 0; mi < 2; mi++) {
#pragma unroll
        for (int rh = 0; rh < 2; rh++) {
            int px = wid*32 + mi*16 + (lane >> 2) + rh*8;
            float v[7][2];
            float ls = 0.f;
#pragma unroll
            for (int ni = 0; ni < 7; ni++) {
                int col = ni*8 + colb;
                v[ni][0] = d2[mi][ni][rh*2 + 0] + s_b2[col];
                v[ni][1] = d2[mi][ni][rh*2 + 1] + s_b2[col + 1];
                ls += v[ni][0] + v[ni][1];
            }
            ls += __shfl_xor_sync(0xffffffff, ls, 1);
            ls += __shfl_xor_sync(0xffffffff, ls, 2);
            float m = ls * (1.0f/49.0f);
            float* rowp = lpb + (size_t)px*52;
#pragma unroll
            for (int ni = 0; ni < 7; ni++) {
                int col = ni*8 + colb;
                if (col < 52) {
                    float2 o = make_float2(v[ni][0] - m + (1.0f/49.0f),
                                           v[ni][1] - m + (1.0f/49.0f));
                    *(float2*)(rowp + col) = o;
                }
            }
        }
    }
}

// ---------------------------------------------------------------------------
// dynamic 7x7 local conv + residual; feat = fp*mp computed during staging.
// ---------------------------------------------------------------------------
#define TILE 16
__global__ __launch_bounds__(256, 2)
void local_conv_kernel(const float* __restrict__ x,
                       const float* __restrict__ fp, const float* __restrict__ mp,
                       const float* __restrict__ lp, float* __restrict__ out)
{
    __shared__ alignas(16) float s_f[2][22*22*10];
    const int b  = blockIdx.z;
    const int x0 = blockIdx.x * TILE;
    const int y0 = blockIdx.y * TILE;
    const int tid = threadIdx.x;
    const int tx = tid & 15, ty = tid >> 4;
    const int y = y0 + ty, xx = x0 + tx;

    float kl[TAPS];
    {
        const float4* klb = (const float4*)(lp + (size_t)(b*HWq + y*Wq + xx)*52);
        float4 t[13];
#pragma unroll
        for (int q = 0; q < 13; q++) t[q] = __ldg(klb + q);
#pragma unroll
        for (int k = 0; k < TAPS; k++) kl[k] = ((const float*)t)[k];
    }

    const float* fpb = fp + b*CHWq;
    const float* mpb = mp + b*CHWq;
    const float* xb  = x  + b*CHWq;
    float*       ob  = out + b*CHWq;

    float4 pv[2][2];
    auto preloadF = [&](int oct) {
#pragma unroll
        for (int s = 0; s < 2; s++) {
            int idx = tid + s*256;
            if (idx < 484) {
                int r  = idx / 22;
                int cc = idx - r*22;
                int gy = y0 + r - 3, gx = x0 + cc - 3;
                if (gy >= 0 && gy < Hq && gx >= 0 && gx < Wq) {
                    const float4* pf = (const float4*)(fpb + oct*HW8 + (gy*Wq + gx)*8);
                    const float4* pm = (const float4*)(mpb + oct*HW8 + (gy*Wq + gx)*8);
                    float4 a0 = __ldg(pf), a1 = __ldg(pf + 1);
                    float4 m0 = __ldg(pm), m1 = __ldg(pm + 1);
                    pv[s][0] = make_float4(a0.x*m0.x, a0.y*m0.y, a0.z*m0.z, a0.w*m0.w);
                    pv[s][1] = make_float4(a1.x*m1.x, a1.y*m1.y, a1.z*m1.z, a1.w*m1.w);
                } else {
                    pv[s][0] = make_float4(0.f, 0.f, 0.f, 0.f);
                    pv[s][1] = make_float4(0.f, 0.f, 0.f, 0.f);
                }
            }
        }
    };
    auto storeF = [&](int buf) {
#pragma unroll
        for (int s = 0; s < 2; s++) {
            int idx = tid + s*256;
            if (idx < 484) {
                float* dst = &s_f[buf][idx*10];
                *(float2*)(dst + 0) = make_float2(pv[s][0].x, pv[s][0].y);
                *(float2*)(dst + 2) = make_float2(pv[s][0].z, pv[s][0].w);
                *(float2*)(dst + 4) = make_float2(pv[s][1].x, pv[s][1].y);
                *(float2*)(dst + 6) = make_float2(pv[s][1].z, pv[s][1].w);
            }
        }
    };

    preloadF(0);
    storeF(0);

    for (int oct = 0; oct < 8; oct++) {
        const int buf = oct & 1;
        __syncthreads();
        if (oct + 1 < 8) preloadF(oct + 1);

        unsigned long long acc2[4] = {0ULL, 0ULL, 0ULL, 0ULL};
#pragma unroll
        for (int dy = 0; dy < KK; dy++) {
#pragma unroll
            for (int dx = 0; dx < KK; dx++) {
                unsigned long long kd = dup2(kl[dy*KK + dx]);
                const unsigned long long* q =
                    (const unsigned long long*)&s_f[buf][((ty + dy)*22 + tx + dx)*10];
                fma2(acc2[0], q[0], kd);
                fma2(acc2[1], q[1], kd);
                fma2(acc2[2], q[2], kd);
                fma2(acc2[3], q[3], kd);
            }
        }

        if (oct + 1 < 8) storeF(buf ^ 1);

#pragma unroll
        for (int j = 0; j < 4; j++) {
            float2 f = unpack2(acc2[j]);
            int off0 = (oct*8 + 2*j)*HWq + y*Wq + xx;
            ob[off0]       = xb[off0]       + f.x;
            ob[off0 + HWq] = xb[off0 + HWq] + f.y;
        }
    }
}

// ---------------------------------------------------------------------------
extern "C" void kernel_launch(void* const* d_in, const int* in_sizes, int n_in,
                              void* d_out, int out_size)
{
    const float* x   = (const float*)d_in[0];
    const float* kf  = (const float*)d_in[1];
    const float* fw1 = (const float*)d_in[2];
    const float* fb1 = (const float*)d_in[3];
    const float* fw2 = (const float*)d_in[4];
    const float* fb2 = (const float*)d_in[5];
    const float* mw1 = (const float*)d_in[6];
    const float* mb1 = (const float*)d_in[7];
    const float* mw2 = (const float*)d_in[8];
    const float* mb2 = (const float*)d_in[9];
    const float* lw1 = (const float*)d_in[10];
    const float* lb1 = (const float*)d_in[11];
    const float* lw2 = (const float*)d_in[12];
    const float* lb2 = (const float*)d_in[13];
    float* out = (float*)d_out;

    float *b1fp, *b1mp, *b2fp, *b2mp, *lpp;
    float2 *wBp, *wL1p, *wL2p;
    cudaGetSymbolAddress((void**)&b1fp, g_b1f);
    cudaGetSymbolAddress((void**)&b1mp, g_b1m);
    cudaGetSymbolAddress((void**)&b2fp, g_b2f);
    cudaGetSymbolAddress((void**)&b2mp, g_b2m);
    cudaGetSymbolAddress((void**)&lpp,  g_lp);
    cudaGetSymbolAddress((void**)&wBp,  g_wB2);
    cudaGetSymbolAddress((void**)&wL1p, g_wL1);
    cudaGetSymbolAddress((void**)&wL2p, g_wL2);

    dim3 cblk(256);
    prep_wt_all_kernel<<<(4*WB2_CONV + 3840)/256 + 1, cblk>>>(
        fw1, fw2, mw1, mw2, lw1, lw2, wBp, wL1p, wL2p);

    lp_mma_kernel<<<dim3(Hq, Bq), 128>>>(kf, wL1p, wL2p, lb1, lb2, lpp);

    dim3 tgrid(Hq, 2*Bq);   // 1024 CTAs per stage
    dim3 tblk(128);
    const float2* wf1 = wBp + 0*WB2_CONV;
    const float2* wf2 = wBp + 1*WB2_CONV;
    const float2* wm1 = wBp + 2*WB2_CONV;
    const float2* wm2 = wBp + 3*WB2_CONV;

    // stage 1: NCHW inputs, relu(x) fused on path A
    conv_mma_kernel<true,  true ><<<tgrid, tblk>>>(
        x, kf, wf1, wm1, fb1, mb1, b1fp, b1mp);
    // stage 2: NHWC8 inputs
    conv_mma_kernel<false, false><<<tgrid, tblk>>>(
        b1fp, b1mp, wf2, wm2, fb2, mb2, b2fp, b2mp);

    dim3 lgrid(Wq/TILE, Hq/TILE, Bq);
    local_conv_kernel<<<lgrid, cblk>>>(x, b2fp, b2mp, lpp, out);
}

// round 17
// speedup vs baseline: 1.8803x; 1.0026x over previous
#include <cuda_runtime.h>
#include <cstdint>

#define Bq 4
#define Cq 64
#define Hq 128
#define Wq 128
#define HWq (Hq*Wq)
#define CHWq (Cq*HWq)
#define HW8 (HWq*8)
#define KK 7
#define TAPS 49
#define NGRP 24
#define NKB  72
#define WB2_CONV (NKB*256)

// scratch (allocation-free rule: __device__ globals). NHWC8 for intermediates.
__device__ float  g_b1f[Bq*CHWq];
__device__ float  g_b1m[Bq*CHWq];
__device__ float  g_b2f[Bq*CHWq];
__device__ float  g_b2m[Bq*CHWq];
__device__ float  g_lp [Bq*HWq*52];     // [b][hw][52] tap-innermost
__device__ float2 g_wB2[4*WB2_CONV];
__device__ float2 g_wL1[2048];
__device__ float2 g_wL2[1792];

// ---------------------------------------------------------------------------
__device__ __forceinline__ uint32_t tf32_hi(float v) {
    uint32_t r; asm("cvt.rna.tf32.f32 %0, %1;" : "=r"(r) : "f"(v)); return r;
}
__device__ __forceinline__ float tf32f(float v) {
    return __uint_as_float(tf32_hi(v));
}
__device__ __forceinline__ void cp16(void* dst, const void* src) {
    unsigned d = (unsigned)__cvta_generic_to_shared(dst);
    asm volatile("cp.async.ca.shared.global [%0], [%1], 16;" :: "r"(d), "l"(src));
}
#define CP_COMMIT asm volatile("cp.async.commit_group;")
#define CP_WAIT0  asm volatile("cp.async.wait_group 0;")

__device__ __forceinline__ void mma_tf32(float d[4], const uint32_t a[4],
                                         uint32_t b0, uint32_t b1)
{
    asm volatile(
        "mma.sync.aligned.m16n8k8.row.col.f32.tf32.tf32.f32 "
        "{%0,%1,%2,%3}, {%4,%5,%6,%7}, {%8,%9}, {%0,%1,%2,%3};"
        : "+f"(d[0]), "+f"(d[1]), "+f"(d[2]), "+f"(d[3])
        : "r"(a[0]), "r"(a[1]), "r"(a[2]), "r"(a[3]), "r"(b0), "r"(b1));
}
__device__ __forceinline__ unsigned long long dup2(float a) {
    unsigned long long r;
    asm("mov.b64 %0, {%1, %1};" : "=l"(r) : "f"(a)); return r;
}
__device__ __forceinline__ void fma2(unsigned long long& d,
                                     unsigned long long a, unsigned long long b) {
    asm("fma.rn.f32x2 %0, %1, %2, %0;" : "+l"(d) : "l"(a), "l"(b));
}
__device__ __forceinline__ float2 unpack2(unsigned long long v) {
    float2 f;
    asm("mov.b64 {%0, %1}, %2;" : "=f"(f.x), "=f"(f.y) : "l"(v)); return f;
}

// ---------------------------------------------------------------------------
// all weight packing in one launch: conv frags then lp frags
// ---------------------------------------------------------------------------
__global__ void prep_wt_all_kernel(
    const float* __restrict__ w0, const float* __restrict__ w1,
    const float* __restrict__ w2, const float* __restrict__ w3,
    const float* __restrict__ lw1, const float* __restrict__ lw2,
    float2* __restrict__ wB2, float2* __restrict__ wL1, float2* __restrict__ wL2)
{
    int i = blockIdx.x*256 + threadIdx.x;
    if (i < 4*WB2_CONV) {
        int conv = i / WB2_CONV;
        int r    = i - conv*WB2_CONV;
        int kb   = r >> 8;
        int r2   = r & 255;
        int nb   = r2 >> 5;
        int lane = r2 & 31;
        int g  = kb / 3, dx = kb - g*3;
        int dy = g >> 3, oct = g & 7;
        int tap = dy*3 + dx;
        int n   = nb*8 + (lane >> 2);
        int ci0 = oct*8 + (lane & 3);
        const float* w = (conv == 0) ? w0 : (conv == 1) ? w1 : (conv == 2) ? w2 : w3;
        float v0 = w[(n*Cq + ci0    )*9 + tap];
        float v1 = w[(n*Cq + ci0 + 4)*9 + tap];
        wB2[i] = make_float2(tf32f(v0), tf32f(v1));
    } else {
        int j = i - 4*WB2_CONV;
        if (j < 2048) {
            int kb = j >> 8, r2 = j & 255, nb = r2 >> 5, lane = r2 & 31;
            int n = nb*8 + (lane >> 2), ci = kb*8 + (lane & 3);
            wL1[j] = make_float2(tf32f(lw1[n*64 + ci]), tf32f(lw1[n*64 + ci + 4]));
        } else if (j < 3840) {
            int q = j - 2048;
            int kb = q / 224, r2 = q - kb*224, nb = r2 >> 5, lane = r2 & 31;
            int n = nb*8 + (lane >> 2), ci = kb*8 + (lane & 3);
            float v0 = (n < 49) ? lw2[n*64 + ci]     : 0.f;
            float v1 = (n < 49) ? lw2[n*64 + ci + 4] : 0.f;
            wL2[q] = make_float2(tf32f(v0), tf32f(v1));
        }
    }
}

// ---------------------------------------------------------------------------
// conv3x3 via mma.sync tf32 1-pass. R12 configuration (128 thr, 1 row/CTA,
// occ 4, two barriers per group). RAW_IN=true: inputs NCHW, relu fused on
// path A (stage 1). RAW_IN=false: NHWC8 inputs (stage 2). Output NHWC8.
// ---------------------------------------------------------------------------
template<bool RAW_IN, bool RELU_OUT>
__global__ __launch_bounds__(128, 4)
void conv_mma_kernel(const float* __restrict__ inA, const float* __restrict__ inB,
                     const float2* __restrict__ wBA, const float2* __restrict__ wBB,
                     const float* __restrict__ biasA, const float* __restrict__ biasB,
                     float* __restrict__ outA, float* __restrict__ outB)
{
    __shared__ alignas(16) float  sA[2][130*8];
    __shared__ alignas(16) float2 sB[2][768];

    const int y  = blockIdx.x;
    const int z  = blockIdx.y;
    const int b  = z & 3;
    const bool pB = (z >= 4);
    const float*  in   = (pB ? inB  : inA) + b*CHWq;
    const float2* wB   =  pB ? wBB  : wBA;
    const float*  bias =  pB ? biasB : biasA;
    float*        out  = (pB ? outB : outA) + b*CHWq;

    const int tid  = threadIdx.x;
    const int wid  = tid >> 5;
    const int lane = tid & 31;

    if (tid < 32) {
        int bb = tid >> 4, rr = (tid >> 3) & 1, cc = tid & 7;
        sA[bb][(rr ? 129*8 : 0) + cc] = 0.f;
    }

    float d[2][8][4];
#pragma unroll
    for (int mi = 0; mi < 2; mi++)
#pragma unroll
        for (int ni = 0; ni < 8; ni++)
#pragma unroll
            for (int r = 0; r < 4; r++) d[mi][ni][r] = 0.f;

    float v[8];
    auto preloadA = [&](int g) {
        int dy = g >> 3, oct = g & 7;
        int yin = y + dy - 1;
        if (yin >= 0 && yin < Hq) {
            if (RAW_IN) {
                const float* p = in + oct*8*HWq + yin*Wq + tid;
#pragma unroll
                for (int i = 0; i < 8; i++) {
                    float t = __ldg(p + i*HWq);
                    v[i] = pB ? t : fmaxf(t, 0.f);
                }
            } else {
                const float4* p = (const float4*)(in + oct*HW8 + (yin*Wq + tid)*8);
                float4 a0 = __ldg(p), a1 = __ldg(p + 1);
                v[0] = a0.x; v[1] = a0.y; v[2] = a0.z; v[3] = a0.w;
                v[4] = a1.x; v[5] = a1.y; v[6] = a1.z; v[7] = a1.w;
            }
        } else {
#pragma unroll
            for (int i = 0; i < 8; i++) v[i] = 0.f;
        }
    };
    auto storeA = [&](int buf) {
        int px = tid + 1;
        int sw = (px >> 2) & 1;
        float* base = &sA[buf][px*8];
        float4 p0 = make_float4(tf32f(v[0]), tf32f(v[4]), tf32f(v[1]), tf32f(v[5]));
        float4 p1 = make_float4(tf32f(v[2]), tf32f(v[6]), tf32f(v[3]), tf32f(v[7]));
        *(float4*)(base + ((0 ^ sw) << 2)) = p0;
        *(float4*)(base + ((1 ^ sw) << 2)) = p1;
    };
    auto stageB = [&](int buf, int g) {
        const float4* src = (const float4*)(wB + g*768);
        float4* dst = (float4*)sB[buf];
        cp16(dst + tid,       src + tid);
        cp16(dst + 128 + tid, src + 128 + tid);
        cp16(dst + 256 + tid, src + 256 + tid);
        CP_COMMIT;
    };

    preloadA(0);
    storeA(0);
    stageB(0, 0);

    for (int g = 0; g < NGRP; g++) {
        const int buf = g & 1;
        CP_WAIT0;
        __syncthreads();
        if (g + 1 < NGRP) { stageB(buf ^ 1, g + 1); preloadA(g + 1); }

#pragma unroll
        for (int dx = 0; dx < 3; dx++) {
            uint32_t a[2][4];
#pragma unroll
            for (int mi = 0; mi < 2; mi++) {
                int pxl = wid*32 + mi*16 + (lane >> 2) + dx;
                int c   = lane & 3;
                int sw  = (pxl >> 2) & 1;
                int off = (((c >> 1) ^ sw) << 2) + ((c & 1) << 1);
                float2 q0 = *(float2*)&sA[buf][pxl*8 + off];
                float2 q1 = *(float2*)&sA[buf][(pxl + 8)*8 + off];
                a[mi][0] = __float_as_uint(q0.x);
                a[mi][2] = __float_as_uint(q0.y);
                a[mi][1] = __float_as_uint(q1.x);
                a[mi][3] = __float_as_uint(q1.y);
            }
#pragma unroll
            for (int ni = 0; ni < 8; ni++) {
                float2 bq = sB[buf][(dx*8 + ni)*32 + lane];
                uint32_t b0 = __float_as_uint(bq.x), b1 = __float_as_uint(bq.y);
#pragma unroll
                for (int mi = 0; mi < 2; mi++)
                    mma_tf32(d[mi][ni], a[mi], b0, b1);
            }
        }

        if (g + 1 < NGRP) storeA(buf ^ 1);
        __syncthreads();
    }

    const int row  = lane >> 2;
    const int colb = (lane & 3) << 1;
#pragma unroll
    for (int mi = 0; mi < 2; mi++) {
        int px0 = wid*32 + mi*16 + row;
#pragma unroll
        for (int ni = 0; ni < 8; ni++) {
            float b0 = __ldg(bias + ni*8 + colb);
            float b1 = __ldg(bias + ni*8 + colb + 1);
            float2 r0 = make_float2(d[mi][ni][0] + b0, d[mi][ni][1] + b1);
            float2 r1 = make_float2(d[mi][ni][2] + b0, d[mi][ni][3] + b1);
            if (RELU_OUT) {
                r0.x = fmaxf(r0.x, 0.f); r0.y = fmaxf(r0.y, 0.f);
                r1.x = fmaxf(r1.x, 0.f); r1.y = fmaxf(r1.y, 0.f);
            }
            float* o8 = out + ni*HW8;
            *(float2*)(o8 + (y*Wq + px0    )*8 + colb) = r0;
            *(float2*)(o8 + (y*Wq + px0 + 8)*8 + colb) = r1;
        }
    }
}

// ---------------------------------------------------------------------------
// lp path via mma.sync tf32; kf read directly from NCHW.
// ---------------------------------------------------------------------------
__global__ __launch_bounds__(128, 3)
void lp_mma_kernel(const float* __restrict__ kf,
                   const float2* __restrict__ wL1, const float2* __restrict__ wL2,
                   const float* __restrict__ b1, const float* __restrict__ b2,
                   float* __restrict__ lp)
{
    __shared__ alignas(16) float sU[8192];
    __shared__ float s_b1[64];
    __shared__ float s_b2[56];

    const int y = blockIdx.x, b = blockIdx.y;
    const int tid = threadIdx.x, wid = tid >> 5, lane = tid & 31;
    const float* kfb = kf + b*CHWq;

    if (tid < 64) s_b1[tid] = b1[tid];
    if (tid < 56) s_b2[tid] = (tid < 49) ? b2[tid] : 0.f;

    {
        int px = tid, sw = (px >> 2) & 1;
#pragma unroll
        for (int oct = 0; oct < 8; oct++) {
            const float* p = kfb + oct*8*HWq + y*Wq + px;
            float u[8];
#pragma unroll
            for (int i = 0; i < 8; i++) u[i] = __ldg(p + i*HWq);
            float* base = &sU[oct*1024 + px*8];
            float4 p0 = make_float4(tf32f(u[0]), tf32f(u[4]), tf32f(u[1]), tf32f(u[5]));
            float4 p1 = make_float4(tf32f(u[2]), tf32f(u[6]), tf32f(u[3]), tf32f(u[7]));
            *(float4*)(base + ((0 ^ sw) << 2)) = p0;
            *(float4*)(base + ((1 ^ sw) << 2)) = p1;
        }
    }
    __syncthreads();

    float d1[2][8][4];
#pragma unroll
    for (int mi = 0; mi < 2; mi++)
#pragma unroll
        for (int ni = 0; ni < 8; ni++)
#pragma unroll
            for (int r = 0; r < 4; r++) d1[mi][ni][r] = 0.f;

#pragma unroll
    for (int oct = 0; oct < 8; oct++) {
        uint32_t a[2][4];
#pragma unroll
        for (int mi = 0; mi < 2; mi++) {
            int pxl = wid*32 + mi*16 + (lane >> 2);
            int c = lane & 3, sw = (pxl >> 2) & 1;
            int off = (((c >> 1) ^ sw) << 2) + ((c & 1) << 1);
            float2 q0 = *(float2*)&sU[oct*1024 + pxl*8 + off];
            float2 q1 = *(float2*)&sU[oct*1024 + (pxl + 8)*8 + off];
            a[mi][0] = __float_as_uint(q0.x);
            a[mi][2] = __float_as_uint(q0.y);
            a[mi][1] = __float_as_uint(q1.x);
            a[mi][3] = __float_as_uint(q1.y);
        }
#pragma unroll
        for (int ni = 0; ni < 8; ni++) {
            float2 bq = __ldg(&wL1[(oct*8 + ni)*32 + lane]);
            uint32_t b0 = __float_as_uint(bq.x), b1v = __float_as_uint(bq.y);
#pragma unroll
            for (int mi = 0; mi < 2; mi++)
                mma_tf32(d1[mi][ni], a[mi], b0, b1v);
        }
    }
    __syncthreads();

    {
        const int colb = (lane & 3) << 1;
#pragma unroll
        for (int mi = 0; mi < 2; mi++) {
            int row0 = wid*32 + mi*16 + (lane >> 2);
            int sw   = (row0 >> 2) & 1;
            int blk  = ((((colb & 3) >> 1) ^ sw) << 2);
            int posE = blk + (colb >= 4 ? 1 : 0);
            int posO = blk + 2 + (colb >= 4 ? 1 : 0);
#pragma unroll
            for (int ni = 0; ni < 8; ni++) {
                float bA = s_b1[ni*8 + colb], bB = s_b1[ni*8 + colb + 1];
                float* base = &sU[ni*1024];
                base[row0*8 + posE]       = tf32f(fmaxf(d1[mi][ni][0] + bA, 0.f));
                base[row0*8 + posO]       = tf32f(fmaxf(d1[mi][ni][1] + bB, 0.f));
                base[(row0 + 8)*8 + posE] = tf32f(fmaxf(d1[mi][ni][2] + bA, 0.f));
                base[(row0 + 8)*8 + posO] = tf32f(fmaxf(d1[mi][ni][3] + bB, 0.f));
            }
        }
    }
    __syncthreads();

    float d2[2][7][4];
#pragma unroll
    for (int mi = 0; mi < 2; mi++)
#pragma unroll
        for (int ni = 0; ni < 7; ni++)
#pragma unroll
            for (int r = 0; r < 4; r++) d2[mi][ni][r] = 0.f;

#pragma unroll
    for (int oct = 0; oct < 8; oct++) {
        uint32_t a[2][4];
#pragma unroll
        for (int mi = 0; mi < 2; mi++) {
            int pxl = wid*32 + mi*16 + (lane >> 2);
            int c = lane & 3, sw = (pxl >> 2) & 1;
            int off = (((c >> 1) ^ sw) << 2) + ((c & 1) << 1);
            float2 q0 = *(float2*)&sU[oct*1024 + pxl*8 + off];
            float2 q1 = *(float2*)&sU[oct*1024 + (pxl + 8)*8 + off];
            a[mi][0] = __float_as_uint(q0.x);
            a[mi][2] = __float_as_uint(q0.y);
            a[mi][1] = __float_as_uint(q1.x);
            a[mi][3] = __float_as_uint(q1.y);
        }
#pragma unroll
        for (int ni = 0; ni < 7; ni++) {
            float2 bq = __ldg(&wL2[(oct*7 + ni)*32 + lane]);
            uint32_t b0 = __float_as_uint(bq.x), b1v = __float_as_uint(bq.y);
#pragma unroll
            for (int mi = 0; mi < 2; mi++)
                mma_tf32(d2[mi][ni], a[mi], b0, b1v);
        }
    }

    const int colb = (lane & 3) << 1;
    float* lpb = lp + (size_t)(b*HWq + y*Wq)*52;
#pragma unroll
    for (int mi = 0; mi < 2; mi++) {
#pragma unroll
        for (int rh = 0; rh < 2; rh++) {
            int px = wid*32 + mi*16 + (lane >> 2) + rh*8;
            float v[7][2];
            float ls = 0.f;
#pragma unroll
            for (int ni = 0; ni < 7; ni++) {
                int col = ni*8 + colb;
                v[ni][0] = d2[mi][ni][rh*2 + 0] + s_b2[col];
                v[ni][1] = d2[mi][ni][rh*2 + 1] + s_b2[col + 1];
                ls += v[ni][0] + v[ni][1];
            }
            ls += __shfl_xor_sync(0xffffffff, ls, 1);
            ls += __shfl_xor_sync(0xffffffff, ls, 2);
            float m = ls * (1.0f/49.0f);
            float* rowp = lpb + (size_t)px*52;
#pragma unroll
            for (int ni = 0; ni < 7; ni++) {
                int col = ni*8 + colb;
                if (col < 52) {
                    float2 o = make_float2(v[ni][0] - m + (1.0f/49.0f),
                                           v[ni][1] - m + (1.0f/49.0f));
                    *(float2*)(rowp + col) = o;
                }
            }
        }
    }
}

// ---------------------------------------------------------------------------
// dynamic 7x7 local conv + residual; feat = fp*mp computed during staging.
// Split across channel halves: grid.z = B*2, each CTA does 4 octs (2x
// parallelism vs R16's 256-CTA grid which couldn't fill one wave).
// ---------------------------------------------------------------------------
#define TILE 16
__global__ __launch_bounds__(256, 2)
void local_conv_kernel(const float* __restrict__ x,
                       const float* __restrict__ fp, const float* __restrict__ mp,
                       const float* __restrict__ lp, float* __restrict__ out)
{
    __shared__ alignas(16) float s_f[2][22*22*10];
    const int bz = blockIdx.z;
    const int b    = bz >> 1;
    const int oct0 = (bz & 1) * 4;
    const int x0 = blockIdx.x * TILE;
    const int y0 = blockIdx.y * TILE;
    const int tid = threadIdx.x;
    const int tx = tid & 15, ty = tid >> 4;
    const int y = y0 + ty, xx = x0 + tx;

    float kl[TAPS];
    {
        const float4* klb = (const float4*)(lp + (size_t)(b*HWq + y*Wq + xx)*52);
        float4 t[13];
#pragma unroll
        for (int q = 0; q < 13; q++) t[q] = __ldg(klb + q);
#pragma unroll
        for (int k = 0; k < TAPS; k++) kl[k] = ((const float*)t)[k];
    }

    const float* fpb = fp + b*CHWq;
    const float* mpb = mp + b*CHWq;
    const float* xb  = x  + b*CHWq;
    float*       ob  = out + b*CHWq;

    float4 pv[2][2];
    auto preloadF = [&](int oct) {
#pragma unroll
        for (int s = 0; s < 2; s++) {
            int idx = tid + s*256;
            if (idx < 484) {
                int r  = idx / 22;
                int cc = idx - r*22;
                int gy = y0 + r - 3, gx = x0 + cc - 3;
                if (gy >= 0 && gy < Hq && gx >= 0 && gx < Wq) {
                    const float4* pf = (const float4*)(fpb + oct*HW8 + (gy*Wq + gx)*8);
                    const float4* pm = (const float4*)(mpb + oct*HW8 + (gy*Wq + gx)*8);
                    float4 a0 = __ldg(pf), a1 = __ldg(pf + 1);
                    float4 m0 = __ldg(pm), m1 = __ldg(pm + 1);
                    pv[s][0] = make_float4(a0.x*m0.x, a0.y*m0.y, a0.z*m0.z, a0.w*m0.w);
                    pv[s][1] = make_float4(a1.x*m1.x, a1.y*m1.y, a1.z*m1.z, a1.w*m1.w);
                } else {
                    pv[s][0] = make_float4(0.f, 0.f, 0.f, 0.f);
                    pv[s][1] = make_float4(0.f, 0.f, 0.f, 0.f);
                }
            }
        }
    };
    auto storeF = [&](int buf) {
#pragma unroll
        for (int s = 0; s < 2; s++) {
            int idx = tid + s*256;
            if (idx < 484) {
                float* dst = &s_f[buf][idx*10];
                *(float2*)(dst + 0) = make_float2(pv[s][0].x, pv[s][0].y);
                *(float2*)(dst + 2) = make_float2(pv[s][0].z, pv[s][0].w);
                *(float2*)(dst + 4) = make_float2(pv[s][1].x, pv[s][1].y);
                *(float2*)(dst + 6) = make_float2(pv[s][1].z, pv[s][1].w);
            }
        }
    };

    preloadF(oct0);
    storeF(0);

    for (int oi = 0; oi < 4; oi++) {
        const int oct = oct0 + oi;
        const int buf = oi & 1;
        __syncthreads();
        if (oi + 1 < 4) preloadF(oct + 1);

        unsigned long long acc2[4] = {0ULL, 0ULL, 0ULL, 0ULL};
#pragma unroll
        for (int dy = 0; dy < KK; dy++) {
#pragma unroll
            for (int dx = 0; dx < KK; dx++) {
                unsigned long long kd = dup2(kl[dy*KK + dx]);
                const unsigned long long* q =
                    (const unsigned long long*)&s_f[buf][((ty + dy)*22 + tx + dx)*10];
                fma2(acc2[0], q[0], kd);
                fma2(acc2[1], q[1], kd);
                fma2(acc2[2], q[2], kd);
                fma2(acc2[3], q[3], kd);
            }
        }

        if (oi + 1 < 4) storeF(buf ^ 1);

#pragma unroll
        for (int j = 0; j < 4; j++) {
            float2 f = unpack2(acc2[j]);
            int off0 = (oct*8 + 2*j)*HWq + y*Wq + xx;
            ob[off0]       = xb[off0]       + f.x;
            ob[off0 + HWq] = xb[off0 + HWq] + f.y;
        }
    }
}

// ---------------------------------------------------------------------------
extern "C" void kernel_launch(void* const* d_in, const int* in_sizes, int n_in,
                              void* d_out, int out_size)
{
    const float* x   = (const float*)d_in[0];
    const float* kf  = (const float*)d_in[1];
    const float* fw1 = (const float*)d_in[2];
    const float* fb1 = (const float*)d_in[3];
    const float* fw2 = (const float*)d_in[4];
    const float* fb2 = (const float*)d_in[5];
    const float* mw1 = (const float*)d_in[6];
    const float* mb1 = (const float*)d_in[7];
    const float* mw2 = (const float*)d_in[8];
    const float* mb2 = (const float*)d_in[9];
    const float* lw1 = (const float*)d_in[10];
    const float* lb1 = (const float*)d_in[11];
    const float* lw2 = (const float*)d_in[12];
    const float* lb2 = (const float*)d_in[13];
    float* out = (float*)d_out;

    float *b1fp, *b1mp, *b2fp, *b2mp, *lpp;
    float2 *wBp, *wL1p, *wL2p;
    cudaGetSymbolAddress((void**)&b1fp, g_b1f);
    cudaGetSymbolAddress((void**)&b1mp, g_b1m);
    cudaGetSymbolAddress((void**)&b2fp, g_b2f);
    cudaGetSymbolAddress((void**)&b2mp, g_b2m);
    cudaGetSymbolAddress((void**)&lpp,  g_lp);
    cudaGetSymbolAddress((void**)&wBp,  g_wB2);
    cudaGetSymbolAddress((void**)&wL1p, g_wL1);
    cudaGetSymbolAddress((void**)&wL2p, g_wL2);

    dim3 cblk(256);
    prep_wt_all_kernel<<<(4*WB2_CONV + 3840)/256 + 1, cblk>>>(
        fw1, fw2, mw1, mw2, lw1, lw2, wBp, wL1p, wL2p);

    lp_mma_kernel<<<dim3(Hq, Bq), 128>>>(kf, wL1p, wL2p, lb1, lb2, lpp);

    dim3 tgrid(Hq, 2*Bq);   // 1024 CTAs per stage
    dim3 tblk(128);
    const float2* wf1 = wBp + 0*WB2_CONV;
    const float2* wf2 = wBp + 1*WB2_CONV;
    const float2* wm1 = wBp + 2*WB2_CONV;
    const float2* wm2 = wBp + 3*WB2_CONV;

    // stage 1: NCHW inputs, relu(x) fused on path A
    conv_mma_kernel<true,  true ><<<tgrid, tblk>>>(
        x, kf, wf1, wm1, fb1, mb1, b1fp, b1mp);
    // stage 2: NHWC8 inputs
    conv_mma_kernel<false, false><<<tgrid, tblk>>>(
        b1fp, b1mp, wf2, wm2, fb2, mb2, b2fp, b2mp);

    dim3 lgrid(Wq/TILE, Hq/TILE, Bq*2);   // 512 CTAs
    local_conv_kernel<<<lgrid, cblk>>>(x, b2fp, b2mp, lpp, out);
}